// round 3
// baseline (speedup 1.0000x reference)
#include <cuda_runtime.h>
#include <math.h>
#include <stdint.h>

#define B_  2
#define S_  2048
#define E_  1024
#define H_  16
#define DH_ 64
#define BH_ (B_*H_)

// ---------------------------------------------------------------------------
// Global scratch (allocation-free rule)
// ---------------------------------------------------------------------------
__device__ uint32_t g_xp [(size_t)B_*S_*E_];            // x tf32, sigma-permuted cols [4096][1024]
__device__ uint32_t g_wp [3ull*H_*128*64*8];            // [which][h][k8][n][8] frag pairs
__device__ uint32_t g_wop[(size_t)128*1024*8];          // [k8][n][8]
__device__ float    g_q  [(size_t)BH_*S_*DH_];          // plain [bh][S][64]
__device__ uint32_t g_kp [(size_t)BH_*8*S_*8];          // [bh][dh8][S][8]
__device__ uint32_t g_vp [(size_t)BH_*(S_/8)*DH_*8];    // [bh][key8][64][8]
__device__ uint32_t g_aop[(size_t)B_*S_*E_];            // attn out tf32 perm [4096][1024]

// ---------------------------------------------------------------------------
// helpers
// ---------------------------------------------------------------------------
__device__ __forceinline__ uint32_t f2tf(float f) {
    uint32_t u;
    asm("cvt.rna.tf32.f32 %0, %1;" : "=r"(u) : "f"(f));
    return u;
}

__device__ __forceinline__ int tau(int k) { return 2 * (k & 3) + (k >> 2); }

__device__ __forceinline__ void mma8(float& d0, float& d1, float& d2, float& d3,
                                     uint32_t a0, uint32_t a1, uint32_t a2, uint32_t a3,
                                     uint32_t b0, uint32_t b1) {
    asm volatile(
        "mma.sync.aligned.m16n8k8.row.col.f32.tf32.tf32.f32 "
        "{%0,%1,%2,%3}, {%4,%5,%6,%7}, {%8,%9}, {%0,%1,%2,%3};"
        : "+f"(d0), "+f"(d1), "+f"(d2), "+f"(d3)
        : "r"(a0), "r"(a1), "r"(a2), "r"(a3), "r"(b0), "r"(b1));
}

__device__ __forceinline__ void cpa16(uint32_t dst_smem, const void* src) {
    asm volatile("cp.async.cg.shared.global [%0], [%1], 16;\n"
                 :: "r"(dst_smem), "l"(src));
}
__device__ __forceinline__ void cp_commit() {
    asm volatile("cp.async.commit_group;\n");
}
template<int N> __device__ __forceinline__ void cp_wait() {
    asm volatile("cp.async.wait_group %0;\n" :: "n"(N));
}

// ---------------------------------------------------------------------------
// prep kernels: convert to tf32 in fragment-friendly layouts
// slot order within each 8-block: kappa(tau) = 0,4,1,5,2,6,3,7
// ---------------------------------------------------------------------------
__global__ __launch_bounds__(256) void prep_x(const float* __restrict__ x) {
    int i = blockIdx.x * 256 + threadIdx.x;     // one per 8-col group (4096*128)
    int row = i >> 7, grp = i & 127;
    const float* s = x + (size_t)row * 1024 + grp * 8;
    float4 a = *(const float4*)s;
    float4 b = *(const float4*)(s + 4);
    uint32_t v0 = f2tf(a.x), v1 = f2tf(a.y), v2 = f2tf(a.z), v3 = f2tf(a.w);
    uint32_t v4 = f2tf(b.x), v5 = f2tf(b.y), v6 = f2tf(b.z), v7 = f2tf(b.w);
    uint32_t* d = g_xp + (size_t)row * 1024 + grp * 8;
    uint4 o0 = make_uint4(v0, v4, v1, v5);
    uint4 o1 = make_uint4(v2, v6, v3, v7);
    *(uint4*)d = o0;
    *(uint4*)(d + 4) = o1;
}

__global__ __launch_bounds__(64) void prep_w(const float* __restrict__ wq,
                                             const float* __restrict__ wk,
                                             const float* __restrict__ wv) {
    int blk = blockIdx.x;                 // which*2048 + h*128 + e8
    int which = blk >> 11;
    int h  = (blk >> 7) & 15;
    int e8 = blk & 127;
    const float* w = (which == 0 ? wq : (which == 1 ? wk : wv))
                     + ((size_t)h * 1024 + e8 * 8) * 64;
    int n = threadIdx.x;                  // 0..63
    uint32_t v[8];
#pragma unroll
    for (int kap = 0; kap < 8; kap++) v[kap] = f2tf(w[kap * 64 + n]);
    uint32_t* d = g_wp + ((size_t)blk * 64 + n) * 8;
    uint4 o0 = make_uint4(v[0], v[4], v[1], v[5]);
    uint4 o1 = make_uint4(v[2], v[6], v[3], v[7]);
    *(uint4*)d = o0;
    *(uint4*)(d + 4) = o1;
}

__global__ __launch_bounds__(256) void prep_wo(const float* __restrict__ wo) {
    int e8 = blockIdx.x >> 2;
    int n  = (blockIdx.x & 3) * 256 + threadIdx.x;
    uint32_t v[8];
#pragma unroll
    for (int kap = 0; kap < 8; kap++) v[kap] = f2tf(wo[(size_t)(e8 * 8 + kap) * 1024 + n]);
    uint32_t* d = g_wop + ((size_t)e8 * 1024 + n) * 8;
    uint4 o0 = make_uint4(v[0], v[4], v[1], v[5]);
    uint4 o1 = make_uint4(v[2], v[6], v[3], v[7]);
    *(uint4*)d = o0;
    *(uint4*)(d + 4) = o1;
}

// ---------------------------------------------------------------------------
// Shared GEMM mainloop: 128x64 tile, 4 warps (warp tile 64x32), K in 32-steps,
// cp.async double-buffered. A from sigma-permuted tf32 global (row-major 1024),
// B from fragment-pair layout (bk8stride words per k8 row).
// ---------------------------------------------------------------------------
#define LDA 40
#define GEMM_SMEM_BYTES ((2*128*LDA + 2*2048) * 4)

__device__ __forceinline__ void gemm_main(
    const uint32_t* __restrict__ Ag,     // + m-tile offset, row length 1024
    const uint32_t* __restrict__ Bbase,  // fragment layout base for this n-strip
    size_t bk8stride,
    uint32_t* sA, uint32_t* sB,
    float acc[4][4][4])
{
    const int tid  = threadIdx.x;       // 128
    const int warp = tid >> 5;
    const int lane = tid & 31;
    const int g    = lane >> 2;
    const int tig  = lane & 3;
    const int wm   = (warp >> 1) * 64;
    const int wn   = (warp & 1) * 32;

#pragma unroll
    for (int ms = 0; ms < 4; ms++)
#pragma unroll
        for (int nt = 0; nt < 4; nt++)
#pragma unroll
            for (int r = 0; r < 4; r++) acc[ms][nt][r] = 0.f;

    const uint32_t sA_addr = (uint32_t)__cvta_generic_to_shared(sA);
    const uint32_t sB_addr = (uint32_t)__cvta_generic_to_shared(sB);

    // --- tile copy (A: thread=row, 8x16B; B: 4 chunks of 2KB, 4x16B/thread)
    auto copy_tile = [&](int k0, int buf) {
        uint32_t dA = sA_addr + (uint32_t)buf * (128 * LDA * 4) + (uint32_t)tid * (LDA * 4);
        const uint32_t* srcA = Ag + (size_t)tid * 1024 + k0;
#pragma unroll
        for (int j = 0; j < 8; j++) cpa16(dA + j * 16, srcA + j * 4);
        const uint32_t* srcB = Bbase + (size_t)((k0 >> 3) + (tid >> 5)) * bk8stride
                               + (tid & 31) * 16;
        uint32_t dB = sB_addr + (uint32_t)buf * 8192 + (uint32_t)(tid >> 5) * 2048
                      + (uint32_t)(tid & 31) * 64;
#pragma unroll
        for (int j = 0; j < 4; j++) cpa16(dB + j * 16, srcB + j * 4);
        cp_commit();
    };

    copy_tile(0, 0);

    int it = 0;
    for (int k0 = 0; k0 < 1024; k0 += 32, it ^= 1) {
        __syncthreads();                    // prev compute done -> other buf free
        if (k0 + 32 < 1024) { copy_tile(k0 + 32, it ^ 1); cp_wait<1>(); }
        else                { cp_wait<0>(); }
        __syncthreads();

        const uint32_t* A  = sA + it * 128 * LDA;
        const uint32_t* Bt = sB + it * 2048;
#pragma unroll
        for (int kk = 0; kk < 4; kk++) {
            uint32_t af[4][4];
#pragma unroll
            for (int ms = 0; ms < 4; ms++) {
                const uint32_t* ap = A + (wm + 16 * ms + g) * LDA + kk * 8 + 2 * tig;
                uint2 lo = *(const uint2*)ap;
                uint2 hi = *(const uint2*)(ap + 8 * LDA);
                af[ms][0] = lo.x; af[ms][1] = hi.x; af[ms][2] = lo.y; af[ms][3] = hi.y;
            }
#pragma unroll
            for (int nt = 0; nt < 4; nt++) {
                uint2 b = *(const uint2*)(Bt + kk * 512 + (wn + 8 * nt + g) * 8 + 2 * tig);
#pragma unroll
                for (int ms = 0; ms < 4; ms++)
                    mma8(acc[ms][nt][0], acc[ms][nt][1], acc[ms][nt][2], acc[ms][nt][3],
                         af[ms][0], af[ms][1], af[ms][2], af[ms][3], b.x, b.y);
            }
        }
    }
}

// ---------------------------------------------------------------------------
// QKV kernel: grid (16, 32, 3), block 128. Epilogues write q plain, k/v in
// fragment-pair layouts.
// ---------------------------------------------------------------------------
extern __shared__ uint32_t dynsmem[];

__global__ __launch_bounds__(128) void qkv_kernel(
    const float* __restrict__ bq, const float* __restrict__ bk,
    const float* __restrict__ bv)
{
    const int which = blockIdx.z;
    const int bh = blockIdx.y;
    const int b  = bh >> 4;
    const int h  = bh & (H_ - 1);
    const int m0 = blockIdx.x * 128;      // within S

    const uint32_t* Ag = g_xp + ((size_t)b * S_ + m0) * 1024;
    const uint32_t* Bbase = g_wp + (size_t)((which * 16 + h) * 128) * 512;
    const float* bias = (which == 0 ? bq : (which == 1 ? bk : bv)) + h * 64;

    uint32_t* sA = dynsmem;
    uint32_t* sB = dynsmem + 2 * 128 * LDA;

    float acc[4][4][4];
    gemm_main(Ag, Bbase, 512, sA, sB, acc);

    const int tid  = threadIdx.x;
    const int warp = tid >> 5;
    const int lane = tid & 31;
    const int g    = lane >> 2;
    const int tig  = lane & 3;
    const int wm   = (warp >> 1) * 64;
    const int wn   = (warp & 1) * 32;

#pragma unroll
    for (int ms = 0; ms < 4; ms++) {
#pragma unroll
        for (int nt = 0; nt < 4; nt++) {
            const int r0 = m0 + wm + 16 * ms + g;
            const int r1 = r0 + 8;
            const int c  = wn + 8 * nt + 2 * tig;
            const float bx = __ldg(&bias[c]);
            const float by = __ldg(&bias[c + 1]);
            const float v00 = acc[ms][nt][0] + bx, v01 = acc[ms][nt][1] + by;
            const float v10 = acc[ms][nt][2] + bx, v11 = acc[ms][nt][3] + by;

            if (which == 0) {
                float* qp = g_q + ((size_t)bh * S_) * 64;
                *(float2*)(qp + (size_t)r0 * 64 + c) = make_float2(v00, v01);
                *(float2*)(qp + (size_t)r1 * 64 + c) = make_float2(v10, v11);
            } else if (which == 1) {
                // kp[bh][c/8][row][tau(c%8)]
                const size_t base = ((size_t)bh * 8 + (c >> 3)) * (S_ * 8);
                const int t0 = tau(c & 7), t1 = tau((c + 1) & 7);
                g_kp[base + (size_t)r0 * 8 + t0] = f2tf(v00);
                g_kp[base + (size_t)r0 * 8 + t1] = f2tf(v01);
                g_kp[base + (size_t)r1 * 8 + t0] = f2tf(v10);
                g_kp[base + (size_t)r1 * 8 + t1] = f2tf(v11);
            } else {
                // vp[bh][row/8][c][tau(row%8)]
                const size_t base = (size_t)bh * ((S_ / 8) * 64 * 8);
                const int tg = tau(g);     // r0%8 == r1%8 == g
                g_vp[base + (size_t)(r0 >> 3) * 512 + (size_t)c * 8 + tg]       = f2tf(v00);
                g_vp[base + (size_t)(r0 >> 3) * 512 + (size_t)(c + 1) * 8 + tg] = f2tf(v01);
                g_vp[base + (size_t)(r1 >> 3) * 512 + (size_t)c * 8 + tg]       = f2tf(v10);
                g_vp[base + (size_t)(r1 >> 3) * 512 + (size_t)(c + 1) * 8 + tg] = f2tf(v11);
            }
        }
    }
}

// ---------------------------------------------------------------------------
// Output projection: grid (32, 16), block 128
// ---------------------------------------------------------------------------
__global__ __launch_bounds__(128) void proj_kernel(
    const float* __restrict__ bo, float* __restrict__ out)
{
    const int m0 = blockIdx.x * 128;     // global row 0..4095
    const int n0 = blockIdx.y * 64;

    const uint32_t* Ag = g_aop + (size_t)m0 * 1024;
    const uint32_t* Bbase = g_wop + (size_t)n0 * 8;

    uint32_t* sA = dynsmem;
    uint32_t* sB = dynsmem + 2 * 128 * LDA;

    float acc[4][4][4];
    gemm_main(Ag, Bbase, 1024 * 8, sA, sB, acc);

    const int tid  = threadIdx.x;
    const int warp = tid >> 5;
    const int lane = tid & 31;
    const int g    = lane >> 2;
    const int tig  = lane & 3;
    const int wm   = (warp >> 1) * 64;
    const int wn   = (warp & 1) * 32;

#pragma unroll
    for (int ms = 0; ms < 4; ms++) {
#pragma unroll
        for (int nt = 0; nt < 4; nt++) {
            const int r0 = m0 + wm + 16 * ms + g;
            const int c  = n0 + wn + 8 * nt + 2 * tig;
            const float bx = __ldg(&bo[c]);
            const float by = __ldg(&bo[c + 1]);
            *(float2*)(out + (size_t)r0 * 1024 + c) =
                make_float2(acc[ms][nt][0] + bx, acc[ms][nt][1] + by);
            *(float2*)(out + (size_t)(r0 + 8) * 1024 + c) =
                make_float2(acc[ms][nt][2] + bx, acc[ms][nt][3] + by);
        }
    }
}

// ---------------------------------------------------------------------------
// Flash attention. Block 256 (8 warps), warp = 16 q-rows, key tiles of 64,
// cp.async double-buffered K/V from fragment-pair globals.
// SMEM: Ks[2][4096], Vs[2][4096], P[8][16*72]
// ---------------------------------------------------------------------------
#define LDP 72
#define ATTN_SMEM_WORDS (2*4096 + 2*4096 + 8*16*LDP)
#define ATTN_SMEM_BYTES (ATTN_SMEM_WORDS * 4)

__global__ __launch_bounds__(256) void attn_kernel(const int* __restrict__ mask)
{
    uint32_t* Ks = dynsmem;
    uint32_t* Vs = dynsmem + 2 * 4096;
    uint32_t* Ps = dynsmem + 4 * 4096;

    const int tid  = threadIdx.x;
    const int warp = tid >> 5;
    const int lane = tid & 31;
    const int g    = lane >> 2;
    const int tig  = lane & 3;

    const int bh = blockIdx.y;
    const int b  = bh >> 4;
    const int h  = bh & (H_ - 1);
    const int qbase = blockIdx.x * 128 + warp * 16;

    const float SC = 0.18033688011112158f;   // (1/8) * log2(e)
    const float MB = -1.4426950408889634e9f; // -1e9 * log2(e)

    // persistent Q A-fragments
    const float* qp = g_q + ((size_t)bh * S_ + qbase) * 64;
    uint32_t qf[8][4];
#pragma unroll
    for (int ks = 0; ks < 8; ks++) {
        const int c0 = ks * 8 + tig;
        qf[ks][0] = f2tf(qp[(size_t)g * 64 + c0]);
        qf[ks][1] = f2tf(qp[(size_t)(g + 8) * 64 + c0]);
        qf[ks][2] = f2tf(qp[(size_t)g * 64 + c0 + 4]);
        qf[ks][3] = f2tf(qp[(size_t)(g + 8) * 64 + c0 + 4]);
    }

    float oacc[8][4];
#pragma unroll
    for (int i = 0; i < 8; i++)
#pragma unroll
        for (int j = 0; j < 4; j++) oacc[i][j] = 0.f;
    float rm0 = -1e30f, rm1 = -1e30f;
    float rl0 = 0.f,    rl1 = 0.f;

    const uint32_t ks_addr = (uint32_t)__cvta_generic_to_shared(Ks);
    const uint32_t vs_addr = (uint32_t)__cvta_generic_to_shared(Vs);
    const uint32_t* kp_base = g_kp + (size_t)bh * 8 * S_ * 8;
    const uint32_t* vp_base = g_vp + (size_t)bh * (S_ / 8) * 64 * 8;
    uint32_t* Pw = Ps + warp * 16 * LDP;

    auto copy_kv = [&](int kt, int buf) {
        // K: 8 chunks [dh8][64 keys][8] of 512 words
        const uint32_t* srcK = kp_base + (size_t)(tid >> 5) * (S_ * 8)
                               + (size_t)kt * 8 + (tid & 31) * 16;
        uint32_t dK = ks_addr + (uint32_t)buf * 16384 + (uint32_t)(tid >> 5) * 2048
                      + (uint32_t)(tid & 31) * 64;
#pragma unroll
        for (int j = 0; j < 4; j++) cpa16(dK + j * 16, srcK + j * 4);
        // V: contiguous 4096 words at kt*64
        const uint32_t* srcV = vp_base + (size_t)kt * 64 + tid * 16;
        uint32_t dV = vs_addr + (uint32_t)buf * 16384 + (uint32_t)tid * 64;
#pragma unroll
        for (int j = 0; j < 4; j++) cpa16(dV + j * 16, srcV + j * 4);
        cp_commit();
    };

    copy_kv(0, 0);

    const int* mrow = mask + b * S_;
    int it = 0;
    for (int kt = 0; kt < S_; kt += 64, it ^= 1) {
        __syncthreads();
        if (kt + 64 < S_) { copy_kv(kt + 64, it ^ 1); cp_wait<1>(); }
        else              { cp_wait<0>(); }
        __syncthreads();

        const uint32_t* Kb = Ks + it * 4096;
        const uint32_t* Vb = Vs + it * 4096;

        // ---- scores = Q @ K^T
        float sacc[8][4];
#pragma unroll
        for (int i = 0; i < 8; i++)
#pragma unroll
            for (int j = 0; j < 4; j++) sacc[i][j] = 0.f;
#pragma unroll
        for (int kk = 0; kk < 8; kk++) {
#pragma unroll
            for (int nt = 0; nt < 8; nt++) {
                uint2 bb = *(const uint2*)(Kb + kk * 512 + (nt * 8 + g) * 8 + 2 * tig);
                mma8(sacc[nt][0], sacc[nt][1], sacc[nt][2], sacc[nt][3],
                     qf[kk][0], qf[kk][1], qf[kk][2], qf[kk][3], bb.x, bb.y);
            }
        }

        // ---- scale + mask + tile row-max (exp2 domain)
        float tm0 = -1e30f, tm1 = -1e30f;
#pragma unroll
        for (int nt = 0; nt < 8; nt++) {
            const int mc = kt + nt * 8 + 2 * tig;
            const float m0v = (__ldg(&mrow[mc])     == 0) ? MB : 0.f;
            const float m1v = (__ldg(&mrow[mc + 1]) == 0) ? MB : 0.f;
            sacc[nt][0] = sacc[nt][0] * SC + m0v;
            sacc[nt][1] = sacc[nt][1] * SC + m1v;
            sacc[nt][2] = sacc[nt][2] * SC + m0v;
            sacc[nt][3] = sacc[nt][3] * SC + m1v;
            tm0 = fmaxf(tm0, fmaxf(sacc[nt][0], sacc[nt][1]));
            tm1 = fmaxf(tm1, fmaxf(sacc[nt][2], sacc[nt][3]));
        }
        tm0 = fmaxf(tm0, __shfl_xor_sync(0xffffffff, tm0, 1));
        tm0 = fmaxf(tm0, __shfl_xor_sync(0xffffffff, tm0, 2));
        tm1 = fmaxf(tm1, __shfl_xor_sync(0xffffffff, tm1, 1));
        tm1 = fmaxf(tm1, __shfl_xor_sync(0xffffffff, tm1, 2));

        const float nm0 = fmaxf(rm0, tm0);
        const float nm1 = fmaxf(rm1, tm1);
        const float c0 = exp2f(rm0 - nm0);
        const float c1 = exp2f(rm1 - nm1);
        rm0 = nm0; rm1 = nm1;
        rl0 *= c0;  rl1 *= c1;
#pragma unroll
        for (int nt = 0; nt < 8; nt++) {
            oacc[nt][0] *= c0; oacc[nt][1] *= c0;
            oacc[nt][2] *= c1; oacc[nt][3] *= c1;
        }

        // ---- P = exp2(s - m), stage in permuted layout for LDS.64 A-frags
#pragma unroll
        for (int nt = 0; nt < 8; nt++) {
            const float p0 = exp2f(sacc[nt][0] - nm0);
            const float p1 = exp2f(sacc[nt][1] - nm0);
            const float p2 = exp2f(sacc[nt][2] - nm1);
            const float p3 = exp2f(sacc[nt][3] - nm1);
            rl0 += p0 + p1;
            rl1 += p2 + p3;
            const int s0 = nt * 8 + tau(2 * tig);
            const int s1 = nt * 8 + tau(2 * tig + 1);
            Pw[g * LDP + s0]       = f2tf(p0);
            Pw[g * LDP + s1]       = f2tf(p1);
            Pw[(g + 8) * LDP + s0] = f2tf(p2);
            Pw[(g + 8) * LDP + s1] = f2tf(p3);
        }
        __syncwarp();

        // ---- O += P @ V
#pragma unroll
        for (int kk = 0; kk < 8; kk++) {
            uint2 alo = *(const uint2*)(Pw + g * LDP + kk * 8 + 2 * tig);
            uint2 ahi = *(const uint2*)(Pw + (g + 8) * LDP + kk * 8 + 2 * tig);
#pragma unroll
            for (int nt = 0; nt < 8; nt++) {
                uint2 bb = *(const uint2*)(Vb + kk * 512 + (nt * 8 + g) * 8 + 2 * tig);
                mma8(oacc[nt][0], oacc[nt][1], oacc[nt][2], oacc[nt][3],
                     alo.x, ahi.x, alo.y, ahi.y, bb.x, bb.y);
            }
        }
    }

    rl0 += __shfl_xor_sync(0xffffffff, rl0, 1);
    rl0 += __shfl_xor_sync(0xffffffff, rl0, 2);
    rl1 += __shfl_xor_sync(0xffffffff, rl1, 1);
    rl1 += __shfl_xor_sync(0xffffffff, rl1, 2);
    const float inv0 = 1.f / rl0;
    const float inv1 = 1.f / rl1;

    // write attention output in sigma-permuted tf32 layout for proj
    const size_t row0 = (size_t)b * S_ + qbase + g;
#pragma unroll
    for (int nt = 0; nt < 8; nt++) {
        const int C  = h * 64 + nt * 8 + 2 * tig;
        const int w0 = (C & ~7) + tau(C & 7);
        const int w1 = (C & ~7) + tau((C + 1) & 7);
        g_aop[row0 * 1024 + w0]       = f2tf(oacc[nt][0] * inv0);
        g_aop[row0 * 1024 + w1]       = f2tf(oacc[nt][1] * inv0);
        g_aop[(row0 + 8) * 1024 + w0] = f2tf(oacc[nt][2] * inv1);
        g_aop[(row0 + 8) * 1024 + w1] = f2tf(oacc[nt][3] * inv1);
    }
}

// ---------------------------------------------------------------------------
extern "C" void kernel_launch(void* const* d_in, const int* in_sizes, int n_in,
                              void* d_out, int out_size)
{
    const float* x    = (const float*)d_in[0];
    const int*   mask = (const int*)  d_in[1];
    const float* wq   = (const float*)d_in[2];
    const float* bq   = (const float*)d_in[3];
    const float* wk   = (const float*)d_in[4];
    const float* bk   = (const float*)d_in[5];
    const float* wv   = (const float*)d_in[6];
    const float* bv   = (const float*)d_in[7];
    const float* wo   = (const float*)d_in[8];
    const float* bo   = (const float*)d_in[9];
    float* out = (float*)d_out;

    static bool attrs_set = false;
    if (!attrs_set) {
        cudaFuncSetAttribute(qkv_kernel, cudaFuncAttributeMaxDynamicSharedMemorySize, GEMM_SMEM_BYTES);
        cudaFuncSetAttribute(proj_kernel, cudaFuncAttributeMaxDynamicSharedMemorySize, GEMM_SMEM_BYTES);
        cudaFuncSetAttribute(attn_kernel, cudaFuncAttributeMaxDynamicSharedMemorySize, ATTN_SMEM_BYTES);
        attrs_set = true;
    }

    prep_x <<<(B_ * S_ * E_ / 8) / 256, 256>>>(x);
    prep_w <<<3 * H_ * 128, 64>>>(wq, wk, wv);
    prep_wo<<<128 * 4, 256>>>(wo);

    dim3 g1(S_ / 128, BH_, 3);
    qkv_kernel<<<g1, 128, GEMM_SMEM_BYTES>>>(bq, bk, bv);

    dim3 g2(S_ / 128, BH_);
    attn_kernel<<<g2, 256, ATTN_SMEM_BYTES>>>(mask);

    dim3 g3((B_ * S_) / 128, E_ / 64);
    proj_kernel<<<g3, 128, GEMM_SMEM_BYTES>>>(bo, out);
}

// round 4
// speedup vs baseline: 1.1405x; 1.1405x over previous
#include <cuda_runtime.h>
#include <math.h>
#include <stdint.h>

#define B_  2
#define S_  2048
#define E_  1024
#define H_  16
#define DH_ 64
#define BH_ (B_*H_)

// ---------------------------------------------------------------------------
// Global scratch (allocation-free rule)
// ---------------------------------------------------------------------------
__device__ uint32_t g_xp [(size_t)B_*S_*E_];            // x tf32, sigma-permuted [4096][1024]
__device__ uint32_t g_wc [(size_t)128*3072*8];          // combined QKV W: [k8][n][8] frag pairs
__device__ uint32_t g_wop[(size_t)128*1024*8];          // wo: [k8][n][8]
__device__ float    g_q  [(size_t)BH_*S_*DH_];          // plain [bh][S][64]
__device__ uint32_t g_kp [(size_t)BH_*8*S_*8];          // [bh][dh8][S][8]
__device__ uint32_t g_vp [(size_t)BH_*(S_/8)*DH_*8];    // [bh][key8][64][8]
__device__ uint32_t g_aop[(size_t)B_*S_*E_];            // attn out tf32 perm [4096][1024]

// ---------------------------------------------------------------------------
// helpers
// ---------------------------------------------------------------------------
__device__ __forceinline__ uint32_t f2tf(float f) {
    uint32_t u;
    asm("cvt.rna.tf32.f32 %0, %1;" : "=r"(u) : "f"(f));
    return u;
}

__device__ __forceinline__ int tau(int k) { return 2 * (k & 3) + (k >> 2); }

__device__ __forceinline__ void mma8(float& d0, float& d1, float& d2, float& d3,
                                     uint32_t a0, uint32_t a1, uint32_t a2, uint32_t a3,
                                     uint32_t b0, uint32_t b1) {
    asm volatile(
        "mma.sync.aligned.m16n8k8.row.col.f32.tf32.tf32.f32 "
        "{%0,%1,%2,%3}, {%4,%5,%6,%7}, {%8,%9}, {%0,%1,%2,%3};"
        : "+f"(d0), "+f"(d1), "+f"(d2), "+f"(d3)
        : "r"(a0), "r"(a1), "r"(a2), "r"(a3), "r"(b0), "r"(b1));
}

__device__ __forceinline__ void cpa16(uint32_t dst_smem, const void* src) {
    asm volatile("cp.async.cg.shared.global [%0], [%1], 16;\n"
                 :: "r"(dst_smem), "l"(src));
}
__device__ __forceinline__ void cp_commit() {
    asm volatile("cp.async.commit_group;\n");
}
template<int N> __device__ __forceinline__ void cp_wait() {
    asm volatile("cp.async.wait_group %0;\n" :: "n"(N));
}

// ---------------------------------------------------------------------------
// prep kernels
// ---------------------------------------------------------------------------
__global__ __launch_bounds__(256) void prep_x(const float* __restrict__ x) {
    int i = blockIdx.x * 256 + threadIdx.x;
    int row = i >> 7, grp = i & 127;
    const float* s = x + (size_t)row * 1024 + grp * 8;
    float4 a = *(const float4*)s;
    float4 b = *(const float4*)(s + 4);
    uint32_t* d = g_xp + (size_t)row * 1024 + grp * 8;
    *(uint4*)d       = make_uint4(f2tf(a.x), f2tf(b.x), f2tf(a.y), f2tf(b.y));
    *(uint4*)(d + 4) = make_uint4(f2tf(a.z), f2tf(b.z), f2tf(a.w), f2tf(b.w));
}

// combined QKV weight: col n in [0,3072): which=n>>10, h=(n>>6)&15, d=n&63
__global__ __launch_bounds__(256) void prep_wc(const float* __restrict__ wq,
                                               const float* __restrict__ wk,
                                               const float* __restrict__ wv) {
    int blk = blockIdx.x;            // 128*12
    int k8 = blk / 12;
    int n  = (blk % 12) * 256 + threadIdx.x;
    int which = n >> 10;
    int h = (n >> 6) & 15;
    int d = n & 63;
    const float* w = (which == 0 ? wq : (which == 1 ? wk : wv))
                     + ((size_t)h * 1024 + k8 * 8) * 64 + d;
    uint32_t v[8];
#pragma unroll
    for (int kap = 0; kap < 8; kap++) v[kap] = f2tf(w[kap * 64]);
    uint32_t* o = g_wc + ((size_t)k8 * 3072 + n) * 8;
    *(uint4*)o       = make_uint4(v[0], v[4], v[1], v[5]);
    *(uint4*)(o + 4) = make_uint4(v[2], v[6], v[3], v[7]);
}

__global__ __launch_bounds__(256) void prep_wo(const float* __restrict__ wo) {
    int e8 = blockIdx.x >> 2;
    int n  = (blockIdx.x & 3) * 256 + threadIdx.x;
    uint32_t v[8];
#pragma unroll
    for (int kap = 0; kap < 8; kap++) v[kap] = f2tf(wo[(size_t)(e8 * 8 + kap) * 1024 + n]);
    uint32_t* d = g_wop + ((size_t)e8 * 1024 + n) * 8;
    *(uint4*)d       = make_uint4(v[0], v[4], v[1], v[5]);
    *(uint4*)(d + 4) = make_uint4(v[2], v[6], v[3], v[7]);
}

// ---------------------------------------------------------------------------
// GEMM mainloop: 128x128 tile, 256 threads (8 warps, warp tile 64x32),
// K=1024 in 32-steps, cp.async double-buffered.
// ---------------------------------------------------------------------------
#define LDA 40
#define A_BUF (128*LDA)      // 5120 words
#define B_BUF 4096           // 32k x 128n words
#define GEMM_SMEM_BYTES ((2*A_BUF + 2*B_BUF) * 4)

extern __shared__ uint32_t dynsmem[];

__device__ __forceinline__ void gemm_main(
    const uint32_t* __restrict__ Ag,     // row length 1024 words
    const uint32_t* __restrict__ Bbase,  // frag layout, + n0*8 slice
    size_t bstride,                      // words per k8 row
    float acc[4][4][4])
{
    uint32_t* sA = dynsmem;
    uint32_t* sB = dynsmem + 2 * A_BUF;

    const int tid  = threadIdx.x;
    const int warp = tid >> 5;
    const int lane = tid & 31;
    const int g    = lane >> 2;
    const int tig  = lane & 3;
    const int wm   = (warp >> 2) * 64;
    const int wn   = (warp & 3) * 32;

#pragma unroll
    for (int ms = 0; ms < 4; ms++)
#pragma unroll
        for (int nt = 0; nt < 4; nt++)
#pragma unroll
            for (int r = 0; r < 4; r++) acc[ms][nt][r] = 0.f;

    const uint32_t sA_addr = (uint32_t)__cvta_generic_to_shared(sA);
    const uint32_t sB_addr = (uint32_t)__cvta_generic_to_shared(sB);

    const int arow = tid >> 1;
    const int acol = (tid & 1) * 16;
    const int brow = tid >> 6;            // 0..3
    const int boff = (tid & 63) * 16;

    auto copy_tile = [&](int k0, int buf) {
        uint32_t dA = sA_addr + (uint32_t)buf * (A_BUF * 4)
                      + (uint32_t)arow * (LDA * 4) + (uint32_t)acol * 4;
        const uint32_t* srcA = Ag + (size_t)arow * 1024 + k0 + acol;
#pragma unroll
        for (int j = 0; j < 4; j++) cpa16(dA + j * 16, srcA + j * 4);
        uint32_t dB = sB_addr + (uint32_t)buf * (B_BUF * 4)
                      + (uint32_t)brow * 4096 + (uint32_t)boff * 4;
        const uint32_t* srcB = Bbase + (size_t)((k0 >> 3) + brow) * bstride + boff;
#pragma unroll
        for (int j = 0; j < 4; j++) cpa16(dB + j * 16, srcB + j * 4);
        cp_commit();
    };

    copy_tile(0, 0);

    int it = 0;
    for (int k0 = 0; k0 < 1024; k0 += 32, it ^= 1) {
        __syncthreads();
        if (k0 + 32 < 1024) { copy_tile(k0 + 32, it ^ 1); cp_wait<1>(); }
        else                { cp_wait<0>(); }
        __syncthreads();

        const uint32_t* A  = sA + it * A_BUF;
        const uint32_t* Bt = sB + it * B_BUF;
#pragma unroll
        for (int kk = 0; kk < 4; kk++) {
            uint32_t af[4][4];
#pragma unroll
            for (int ms = 0; ms < 4; ms++) {
                const uint32_t* ap = A + (wm + 16 * ms + g) * LDA + kk * 8 + 2 * tig;
                uint2 lo = *(const uint2*)ap;
                uint2 hi = *(const uint2*)(ap + 8 * LDA);
                af[ms][0] = lo.x; af[ms][1] = hi.x; af[ms][2] = lo.y; af[ms][3] = hi.y;
            }
#pragma unroll
            for (int nt = 0; nt < 4; nt++) {
                uint2 b = *(const uint2*)(Bt + kk * 1024 + (wn + 8 * nt + g) * 8 + 2 * tig);
#pragma unroll
                for (int ms = 0; ms < 4; ms++)
                    mma8(acc[ms][nt][0], acc[ms][nt][1], acc[ms][nt][2], acc[ms][nt][3],
                         af[ms][0], af[ms][1], af[ms][2], af[ms][3], b.x, b.y);
            }
        }
    }
}

// ---------------------------------------------------------------------------
// Fused QKV GEMM: [4096,1024] @ [1024,3072]. grid (32, 24), block 256.
// Epilogue scatters into attention layouts.
// ---------------------------------------------------------------------------
__global__ __launch_bounds__(256, 2) void qkv_kernel(
    const float* __restrict__ bq, const float* __restrict__ bk,
    const float* __restrict__ bv)
{
    const int m0 = blockIdx.x * 128;
    const int n0 = blockIdx.y * 128;

    float acc[4][4][4];
    gemm_main(g_xp + (size_t)m0 * 1024, g_wc + (size_t)n0 * 8, 3072 * 8, acc);

    const int tid  = threadIdx.x;
    const int warp = tid >> 5;
    const int lane = tid & 31;
    const int g    = lane >> 2;
    const int tig  = lane & 3;
    const int wm   = (warp >> 2) * 64;
    const int wn   = (warp & 3) * 32;

#pragma unroll
    for (int ms = 0; ms < 4; ms++) {
#pragma unroll
        for (int nt = 0; nt < 4; nt++) {
            const int r0 = m0 + wm + 16 * ms + g;
            const int r1 = r0 + 8;
            const int C  = n0 + wn + 8 * nt + 2 * tig;
            const int which = C >> 10;
            const int h = (C >> 6) & 15;
            const int d = C & 63;
            const int b  = r0 >> 11;
            const int s0 = r0 & 2047;
            const int s1 = r1 & 2047;
            const int bh = b * 16 + h;

            const float* bp = (which == 0 ? bq : (which == 1 ? bk : bv));
            const float bx = __ldg(&bp[h * 64 + d]);
            const float by = __ldg(&bp[h * 64 + d + 1]);
            const float v00 = acc[ms][nt][0] + bx, v01 = acc[ms][nt][1] + by;
            const float v10 = acc[ms][nt][2] + bx, v11 = acc[ms][nt][3] + by;

            if (which == 0) {
                float* qp = g_q + (size_t)bh * S_ * 64;
                *(float2*)(qp + (size_t)s0 * 64 + d) = make_float2(v00, v01);
                *(float2*)(qp + (size_t)s1 * 64 + d) = make_float2(v10, v11);
            } else if (which == 1) {
                const size_t base = ((size_t)bh * 8 + (d >> 3)) * (S_ * 8);
                const int t0 = tau(d & 7), t1 = tau((d + 1) & 7);
                g_kp[base + (size_t)s0 * 8 + t0] = f2tf(v00);
                g_kp[base + (size_t)s0 * 8 + t1] = f2tf(v01);
                g_kp[base + (size_t)s1 * 8 + t0] = f2tf(v10);
                g_kp[base + (size_t)s1 * 8 + t1] = f2tf(v11);
            } else {
                const size_t base = (size_t)bh * ((S_ / 8) * 512);
                const int tg = tau(g);
                g_vp[base + (size_t)(s0 >> 3) * 512 + (size_t)d * 8 + tg]       = f2tf(v00);
                g_vp[base + (size_t)(s0 >> 3) * 512 + (size_t)(d + 1) * 8 + tg] = f2tf(v01);
                g_vp[base + (size_t)(s1 >> 3) * 512 + (size_t)d * 8 + tg]       = f2tf(v10);
                g_vp[base + (size_t)(s1 >> 3) * 512 + (size_t)(d + 1) * 8 + tg] = f2tf(v11);
            }
        }
    }
}

// ---------------------------------------------------------------------------
// Output projection: [4096,1024] @ [1024,1024]. grid (32, 8), block 256.
// ---------------------------------------------------------------------------
__global__ __launch_bounds__(256, 2) void proj_kernel(
    const float* __restrict__ bo, float* __restrict__ out)
{
    const int m0 = blockIdx.x * 128;
    const int n0 = blockIdx.y * 128;

    float acc[4][4][4];
    gemm_main(g_aop + (size_t)m0 * 1024, g_wop + (size_t)n0 * 8, 1024 * 8, acc);

    const int tid  = threadIdx.x;
    const int warp = tid >> 5;
    const int lane = tid & 31;
    const int g    = lane >> 2;
    const int tig  = lane & 3;
    const int wm   = (warp >> 2) * 64;
    const int wn   = (warp & 3) * 32;

#pragma unroll
    for (int ms = 0; ms < 4; ms++) {
#pragma unroll
        for (int nt = 0; nt < 4; nt++) {
            const int r0 = m0 + wm + 16 * ms + g;
            const int c  = n0 + wn + 8 * nt + 2 * tig;
            const float bx = __ldg(&bo[c]);
            const float by = __ldg(&bo[c + 1]);
            *(float2*)(out + (size_t)r0 * 1024 + c) =
                make_float2(acc[ms][nt][0] + bx, acc[ms][nt][1] + by);
            *(float2*)(out + (size_t)(r0 + 8) * 1024 + c) =
                make_float2(acc[ms][nt][2] + bx, acc[ms][nt][3] + by);
        }
    }
}

// ---------------------------------------------------------------------------
// Flash attention (unchanged from r3). Block 256 (8 warps), warp = 16 q rows,
// key tiles of 64, cp.async double-buffered K/V.
// ---------------------------------------------------------------------------
#define LDP 72
#define ATTN_SMEM_WORDS (2*4096 + 2*4096 + 8*16*LDP)
#define ATTN_SMEM_BYTES (ATTN_SMEM_WORDS * 4)

__global__ __launch_bounds__(256) void attn_kernel(const int* __restrict__ mask)
{
    uint32_t* Ks = dynsmem;
    uint32_t* Vs = dynsmem + 2 * 4096;
    uint32_t* Ps = dynsmem + 4 * 4096;

    const int tid  = threadIdx.x;
    const int warp = tid >> 5;
    const int lane = tid & 31;
    const int g    = lane >> 2;
    const int tig  = lane & 3;

    const int bh = blockIdx.y;
    const int b  = bh >> 4;
    const int h  = bh & (H_ - 1);
    const int qbase = blockIdx.x * 128 + warp * 16;

    const float SC = 0.18033688011112158f;   // (1/8) * log2(e)
    const float MB = -1.4426950408889634e9f; // -1e9 * log2(e)

    const float* qp = g_q + ((size_t)bh * S_ + qbase) * 64;
    uint32_t qf[8][4];
#pragma unroll
    for (int ks = 0; ks < 8; ks++) {
        const int c0 = ks * 8 + tig;
        qf[ks][0] = f2tf(qp[(size_t)g * 64 + c0]);
        qf[ks][1] = f2tf(qp[(size_t)(g + 8) * 64 + c0]);
        qf[ks][2] = f2tf(qp[(size_t)g * 64 + c0 + 4]);
        qf[ks][3] = f2tf(qp[(size_t)(g + 8) * 64 + c0 + 4]);
    }

    float oacc[8][4];
#pragma unroll
    for (int i = 0; i < 8; i++)
#pragma unroll
        for (int j = 0; j < 4; j++) oacc[i][j] = 0.f;
    float rm0 = -1e30f, rm1 = -1e30f;
    float rl0 = 0.f,    rl1 = 0.f;

    const uint32_t ks_addr = (uint32_t)__cvta_generic_to_shared(Ks);
    const uint32_t vs_addr = (uint32_t)__cvta_generic_to_shared(Vs);
    const uint32_t* kp_base = g_kp + (size_t)bh * 8 * S_ * 8;
    const uint32_t* vp_base = g_vp + (size_t)bh * (S_ / 8) * 512;
    uint32_t* Pw = Ps + warp * 16 * LDP;

    auto copy_kv = [&](int kt, int buf) {
        const uint32_t* srcK = kp_base + (size_t)(tid >> 5) * (S_ * 8)
                               + (size_t)kt * 8 + (tid & 31) * 16;
        uint32_t dK = ks_addr + (uint32_t)buf * 16384 + (uint32_t)(tid >> 5) * 2048
                      + (uint32_t)(tid & 31) * 64;
#pragma unroll
        for (int j = 0; j < 4; j++) cpa16(dK + j * 16, srcK + j * 4);
        const uint32_t* srcV = vp_base + (size_t)kt * 64 + tid * 16;
        uint32_t dV = vs_addr + (uint32_t)buf * 16384 + (uint32_t)tid * 64;
#pragma unroll
        for (int j = 0; j < 4; j++) cpa16(dV + j * 16, srcV + j * 4);
        cp_commit();
    };

    copy_kv(0, 0);

    const int* mrow = mask + b * S_;
    int it = 0;
    for (int kt = 0; kt < S_; kt += 64, it ^= 1) {
        __syncthreads();
        if (kt + 64 < S_) { copy_kv(kt + 64, it ^ 1); cp_wait<1>(); }
        else              { cp_wait<0>(); }
        __syncthreads();

        const uint32_t* Kb = Ks + it * 4096;
        const uint32_t* Vb = Vs + it * 4096;

        float sacc[8][4];
#pragma unroll
        for (int i = 0; i < 8; i++)
#pragma unroll
            for (int j = 0; j < 4; j++) sacc[i][j] = 0.f;
#pragma unroll
        for (int kk = 0; kk < 8; kk++) {
#pragma unroll
            for (int nt = 0; nt < 8; nt++) {
                uint2 bb = *(const uint2*)(Kb + kk * 512 + (nt * 8 + g) * 8 + 2 * tig);
                mma8(sacc[nt][0], sacc[nt][1], sacc[nt][2], sacc[nt][3],
                     qf[kk][0], qf[kk][1], qf[kk][2], qf[kk][3], bb.x, bb.y);
            }
        }

        float tm0 = -1e30f, tm1 = -1e30f;
#pragma unroll
        for (int nt = 0; nt < 8; nt++) {
            const int mc = kt + nt * 8 + 2 * tig;
            const float m0v = (__ldg(&mrow[mc])     == 0) ? MB : 0.f;
            const float m1v = (__ldg(&mrow[mc + 1]) == 0) ? MB : 0.f;
            sacc[nt][0] = sacc[nt][0] * SC + m0v;
            sacc[nt][1] = sacc[nt][1] * SC + m1v;
            sacc[nt][2] = sacc[nt][2] * SC + m0v;
            sacc[nt][3] = sacc[nt][3] * SC + m1v;
            tm0 = fmaxf(tm0, fmaxf(sacc[nt][0], sacc[nt][1]));
            tm1 = fmaxf(tm1, fmaxf(sacc[nt][2], sacc[nt][3]));
        }
        tm0 = fmaxf(tm0, __shfl_xor_sync(0xffffffff, tm0, 1));
        tm0 = fmaxf(tm0, __shfl_xor_sync(0xffffffff, tm0, 2));
        tm1 = fmaxf(tm1, __shfl_xor_sync(0xffffffff, tm1, 1));
        tm1 = fmaxf(tm1, __shfl_xor_sync(0xffffffff, tm1, 2));

        const float nm0 = fmaxf(rm0, tm0);
        const float nm1 = fmaxf(rm1, tm1);
        const float c0 = exp2f(rm0 - nm0);
        const float c1 = exp2f(rm1 - nm1);
        rm0 = nm0; rm1 = nm1;
        rl0 *= c0;  rl1 *= c1;
#pragma unroll
        for (int nt = 0; nt < 8; nt++) {
            oacc[nt][0] *= c0; oacc[nt][1] *= c0;
            oacc[nt][2] *= c1; oacc[nt][3] *= c1;
        }

#pragma unroll
        for (int nt = 0; nt < 8; nt++) {
            const float p0 = exp2f(sacc[nt][0] - nm0);
            const float p1 = exp2f(sacc[nt][1] - nm0);
            const float p2 = exp2f(sacc[nt][2] - nm1);
            const float p3 = exp2f(sacc[nt][3] - nm1);
            rl0 += p0 + p1;
            rl1 += p2 + p3;
            const int s0 = nt * 8 + tau(2 * tig);
            const int s1 = nt * 8 + tau(2 * tig + 1);
            Pw[g * LDP + s0]       = f2tf(p0);
            Pw[g * LDP + s1]       = f2tf(p1);
            Pw[(g + 8) * LDP + s0] = f2tf(p2);
            Pw[(g + 8) * LDP + s1] = f2tf(p3);
        }
        __syncwarp();

#pragma unroll
        for (int kk = 0; kk < 8; kk++) {
            uint2 alo = *(const uint2*)(Pw + g * LDP + kk * 8 + 2 * tig);
            uint2 ahi = *(const uint2*)(Pw + (g + 8) * LDP + kk * 8 + 2 * tig);
#pragma unroll
            for (int nt = 0; nt < 8; nt++) {
                uint2 bb = *(const uint2*)(Vb + kk * 512 + (nt * 8 + g) * 8 + 2 * tig);
                mma8(oacc[nt][0], oacc[nt][1], oacc[nt][2], oacc[nt][3],
                     alo.x, ahi.x, alo.y, ahi.y, bb.x, bb.y);
            }
        }
    }

    rl0 += __shfl_xor_sync(0xffffffff, rl0, 1);
    rl0 += __shfl_xor_sync(0xffffffff, rl0, 2);
    rl1 += __shfl_xor_sync(0xffffffff, rl1, 1);
    rl1 += __shfl_xor_sync(0xffffffff, rl1, 2);
    const float inv0 = 1.f / rl0;
    const float inv1 = 1.f / rl1;

    const size_t row0 = (size_t)b * S_ + qbase + g;
#pragma unroll
    for (int nt = 0; nt < 8; nt++) {
        const int C  = h * 64 + nt * 8 + 2 * tig;
        const int w0 = (C & ~7) + tau(C & 7);
        const int w1 = (C & ~7) + tau((C + 1) & 7);
        g_aop[row0 * 1024 + w0]       = f2tf(oacc[nt][0] * inv0);
        g_aop[row0 * 1024 + w1]       = f2tf(oacc[nt][1] * inv0);
        g_aop[(row0 + 8) * 1024 + w0] = f2tf(oacc[nt][2] * inv1);
        g_aop[(row0 + 8) * 1024 + w1] = f2tf(oacc[nt][3] * inv1);
    }
}

// ---------------------------------------------------------------------------
extern "C" void kernel_launch(void* const* d_in, const int* in_sizes, int n_in,
                              void* d_out, int out_size)
{
    const float* x    = (const float*)d_in[0];
    const int*   mask = (const int*)  d_in[1];
    const float* wq   = (const float*)d_in[2];
    const float* bq   = (const float*)d_in[3];
    const float* wk   = (const float*)d_in[4];
    const float* bk   = (const float*)d_in[5];
    const float* wv   = (const float*)d_in[6];
    const float* bv   = (const float*)d_in[7];
    const float* wo   = (const float*)d_in[8];
    const float* bo   = (const float*)d_in[9];
    float* out = (float*)d_out;

    static bool attrs_set = false;
    if (!attrs_set) {
        cudaFuncSetAttribute(qkv_kernel,  cudaFuncAttributeMaxDynamicSharedMemorySize, GEMM_SMEM_BYTES);
        cudaFuncSetAttribute(proj_kernel, cudaFuncAttributeMaxDynamicSharedMemorySize, GEMM_SMEM_BYTES);
        cudaFuncSetAttribute(attn_kernel, cudaFuncAttributeMaxDynamicSharedMemorySize, ATTN_SMEM_BYTES);
        attrs_set = true;
    }

    prep_x <<<(B_ * S_ * E_ / 8) / 256, 256>>>(x);
    prep_wc<<<128 * 12, 256>>>(wq, wk, wv);
    prep_wo<<<128 * 4, 256>>>(wo);

    dim3 g1(S_ * B_ / 128, 3072 / 128);
    qkv_kernel<<<g1, 256, GEMM_SMEM_BYTES>>>(bq, bk, bv);

    dim3 g2(S_ / 128, BH_);
    attn_kernel<<<g2, 256, ATTN_SMEM_BYTES>>>(mask);

    dim3 g3((B_ * S_) / 128, E_ / 128);
    proj_kernel<<<g3, 256, GEMM_SMEM_BYTES>>>(bo, out);
}

// round 5
// speedup vs baseline: 1.4598x; 1.2800x over previous
#include <cuda_runtime.h>
#include <math.h>
#include <stdint.h>

#define B_  2
#define S_  2048
#define E_  1024
#define H_  16
#define DH_ 64
#define BH_ (B_*H_)

// ---------------------------------------------------------------------------
// Global scratch (allocation-free rule)
// ---------------------------------------------------------------------------
__device__ uint32_t g_xp [(size_t)B_*S_*E_];            // x tf32, sigma-permuted [4096][1024]
__device__ uint32_t g_wc [(size_t)128*3072*8];          // combined QKV W: [k8][n][8] frag pairs
__device__ uint32_t g_wop[(size_t)128*1024*8];          // wo: [k8][n][8]
__device__ float    g_q  [(size_t)BH_*S_*DH_];          // plain [bh][S][64]
__device__ float    g_kf [(size_t)BH_*S_*DH_];          // plain K
__device__ float    g_vf [(size_t)BH_*S_*DH_];          // plain V
__device__ uint32_t g_kc [(size_t)BH_*8*S_*8];          // compacted K frag [bh][d8][key][8]
__device__ uint32_t g_vc [(size_t)BH_*(S_/8)*DH_*8];    // compacted V frag [bh][kg][d][8]
__device__ uint32_t g_aop[(size_t)B_*S_*E_];            // attn out tf32 perm [4096][1024]
__device__ int      g_perm[(size_t)B_*S_];              // valid-key gather indices
__device__ int      g_nv[B_];                           // n_valid per batch
__device__ float    g_cmask[(size_t)B_*S_];             // compact mask (0 or -1e9*log2e)

// ---------------------------------------------------------------------------
// helpers
// ---------------------------------------------------------------------------
__device__ __forceinline__ uint32_t f2tf(float f) {
    uint32_t u;
    asm("cvt.rna.tf32.f32 %0, %1;" : "=r"(u) : "f"(f));
    return u;
}

__device__ __forceinline__ int tau(int k) { return 2 * (k & 3) + (k >> 2); }

__device__ __forceinline__ void mma8(float& d0, float& d1, float& d2, float& d3,
                                     uint32_t a0, uint32_t a1, uint32_t a2, uint32_t a3,
                                     uint32_t b0, uint32_t b1) {
    asm volatile(
        "mma.sync.aligned.m16n8k8.row.col.f32.tf32.tf32.f32 "
        "{%0,%1,%2,%3}, {%4,%5,%6,%7}, {%8,%9}, {%0,%1,%2,%3};"
        : "+f"(d0), "+f"(d1), "+f"(d2), "+f"(d3)
        : "r"(a0), "r"(a1), "r"(a2), "r"(a3), "r"(b0), "r"(b1));
}

__device__ __forceinline__ void cpa16(uint32_t dst_smem, const void* src) {
    asm volatile("cp.async.cg.shared.global [%0], [%1], 16;\n"
                 :: "r"(dst_smem), "l"(src));
}
__device__ __forceinline__ void cp_commit() {
    asm volatile("cp.async.commit_group;\n");
}
template<int N> __device__ __forceinline__ void cp_wait() {
    asm volatile("cp.async.wait_group %0;\n" :: "n"(N));
}

// ---------------------------------------------------------------------------
// prep kernels
// ---------------------------------------------------------------------------
__global__ __launch_bounds__(256) void prep_x(const float* __restrict__ x) {
    int i = blockIdx.x * 256 + threadIdx.x;
    int row = i >> 7, grp = i & 127;
    const float* s = x + (size_t)row * 1024 + grp * 8;
    float4 a = *(const float4*)s;
    float4 b = *(const float4*)(s + 4);
    uint32_t* d = g_xp + (size_t)row * 1024 + grp * 8;
    *(uint4*)d       = make_uint4(f2tf(a.x), f2tf(b.x), f2tf(a.y), f2tf(b.y));
    *(uint4*)(d + 4) = make_uint4(f2tf(a.z), f2tf(b.z), f2tf(a.w), f2tf(b.w));
}

__global__ __launch_bounds__(256) void prep_wc(const float* __restrict__ wq,
                                               const float* __restrict__ wk,
                                               const float* __restrict__ wv) {
    int blk = blockIdx.x;            // 128*12
    int k8 = blk / 12;
    int n  = (blk % 12) * 256 + threadIdx.x;
    int which = n >> 10;
    int h = (n >> 6) & 15;
    int d = n & 63;
    const float* w = (which == 0 ? wq : (which == 1 ? wk : wv))
                     + ((size_t)h * 1024 + k8 * 8) * 64 + d;
    uint32_t v[8];
#pragma unroll
    for (int kap = 0; kap < 8; kap++) v[kap] = f2tf(w[kap * 64]);
    uint32_t* o = g_wc + ((size_t)k8 * 3072 + n) * 8;
    *(uint4*)o       = make_uint4(v[0], v[4], v[1], v[5]);
    *(uint4*)(o + 4) = make_uint4(v[2], v[6], v[3], v[7]);
}

__global__ __launch_bounds__(256) void prep_wo(const float* __restrict__ wo) {
    int e8 = blockIdx.x >> 2;
    int n  = (blockIdx.x & 3) * 256 + threadIdx.x;
    uint32_t v[8];
#pragma unroll
    for (int kap = 0; kap < 8; kap++) v[kap] = f2tf(wo[(size_t)(e8 * 8 + kap) * 1024 + n]);
    uint32_t* d = g_wop + ((size_t)e8 * 1024 + n) * 8;
    *(uint4*)d       = make_uint4(v[0], v[4], v[1], v[5]);
    *(uint4*)(d + 4) = make_uint4(v[2], v[6], v[3], v[7]);
}

// ---------------------------------------------------------------------------
// Mask scan: per batch, build gather indices of unmasked keys + compact mask.
// ---------------------------------------------------------------------------
__global__ __launch_bounds__(1024) void scan_mask(const int* __restrict__ mask) {
    __shared__ int buf[2][1024];
    const int b = blockIdx.x, t = threadIdx.x;
    const int m0 = mask[b * 2048 + 2 * t]     != 0;
    const int m1 = mask[b * 2048 + 2 * t + 1] != 0;
    const int sum = m0 + m1;
    buf[0][t] = sum;
    __syncthreads();
    int src = 0;
    for (int off = 1; off < 1024; off <<= 1) {
        int v = buf[src][t];
        if (t >= off) v += buf[src][t - off];
        buf[src ^ 1][t] = v;
        src ^= 1;
        __syncthreads();
    }
    const int incl = buf[src][t];
    const int nv   = buf[src][1023];
    const int excl = incl - sum;
    if (m0) g_perm[b * 2048 + excl]      = 2 * t;
    if (m1) g_perm[b * 2048 + excl + m0] = 2 * t + 1;
    if (t == 0) g_nv[b] = nv;
    const float MBv = -1.4426950408889634e9f;   // -1e9 * log2(e)
    g_cmask[b * 2048 + 2 * t]     = (2 * t     < nv) ? 0.f : MBv;
    g_cmask[b * 2048 + 2 * t + 1] = (2 * t + 1 < nv) ? 0.f : MBv;
}

// ---------------------------------------------------------------------------
// Compact + convert K/V into attention fragment layouts.
// grid (256 key-groups, 32 bh), block 64 (one thread per d).
// ---------------------------------------------------------------------------
__global__ __launch_bounds__(64) void compact_kv() {
    const int bh = blockIdx.y;
    const int b  = bh >> 4;
    const int jg = blockIdx.x;
    const int nv   = g_nv[b];
    const int npad = (nv + 63) & ~63;
    if (jg * 8 >= npad) return;
    __shared__ int sidx[8];
    const int d = threadIdx.x;
    if (d < 8) {
        const int j = jg * 8 + d;
        sidx[d] = (j < nv) ? g_perm[b * 2048 + j] : -1;
    }
    __syncthreads();
    const float* kp = g_kf + (size_t)bh * S_ * 64;
    const float* vp = g_vf + (size_t)bh * S_ * 64;

    // V: thread writes 8 contiguous words [bh][jg][d][0..8)
    uint32_t vw[8];
#pragma unroll
    for (int i = 0; i < 8; i++) {
        const int s = sidx[i];
        const float v = (s >= 0) ? vp[(size_t)s * 64 + d] : 0.f;
        vw[tau(i)] = f2tf(v);
    }
    uint32_t* vdst = g_vc + (((size_t)bh * (S_ / 8) + jg) * 64 + d) * 8;
    *(uint4*)vdst       = make_uint4(vw[0], vw[1], vw[2], vw[3]);
    *(uint4*)(vdst + 4) = make_uint4(vw[4], vw[5], vw[6], vw[7]);

    // K: [bh][d>>3][key][tau(d&7)]
    uint32_t* kdst = g_kc + ((size_t)(bh * 8 + (d >> 3)) * S_ + jg * 8) * 8 + tau(d & 7);
#pragma unroll
    for (int i = 0; i < 8; i++) {
        const int s = sidx[i];
        const float v = (s >= 0) ? kp[(size_t)s * 64 + d] : 0.f;
        kdst[i * 8] = f2tf(v);
    }
}

// ---------------------------------------------------------------------------
// GEMM mainloop: 128x128 tile, 256 threads (8 warps, warp tile 64x32),
// K=1024 in 32-steps, 3-stage cp.async ring, ONE barrier per step.
// ---------------------------------------------------------------------------
#define LDA 40
#define A_BUF (128*LDA)              // 5120 words
#define B_BUF 4096                   // 32k x 128n words
#define STAGE_WORDS (A_BUF + B_BUF)  // 9216
#define GEMM_SMEM_BYTES (3 * STAGE_WORDS * 4)

extern __shared__ uint32_t dynsmem[];

__device__ __forceinline__ void gemm_main(
    const uint32_t* __restrict__ Ag,     // row length 1024 words
    const uint32_t* __restrict__ Bbase,  // frag layout, + n0*8 slice
    size_t bstride,                      // words per k8 row
    float acc[4][4][4])
{
    const int tid  = threadIdx.x;
    const int warp = tid >> 5;
    const int lane = tid & 31;
    const int g    = lane >> 2;
    const int tig  = lane & 3;
    const int wm   = (warp >> 2) * 64;
    const int wn   = (warp & 3) * 32;

#pragma unroll
    for (int ms = 0; ms < 4; ms++)
#pragma unroll
        for (int nt = 0; nt < 4; nt++)
#pragma unroll
            for (int r = 0; r < 4; r++) acc[ms][nt][r] = 0.f;

    const uint32_t sm = (uint32_t)__cvta_generic_to_shared(dynsmem);

    const int arow = tid >> 1;
    const int acol = (tid & 1) * 16;
    const int brow = tid >> 6;            // 0..3
    const int boff = (tid & 63) * 16;

    auto copy_tile = [&](int k0, int st) {
        const uint32_t base = sm + (uint32_t)st * (STAGE_WORDS * 4);
        uint32_t dA = base + (uint32_t)arow * (LDA * 4) + (uint32_t)acol * 4;
        const uint32_t* srcA = Ag + (size_t)arow * 1024 + k0 + acol;
#pragma unroll
        for (int j = 0; j < 4; j++) cpa16(dA + j * 16, srcA + j * 4);
        uint32_t dB = base + A_BUF * 4 + (uint32_t)brow * 4096 + (uint32_t)boff * 4;
        const uint32_t* srcB = Bbase + (size_t)((k0 >> 3) + brow) * bstride + boff;
#pragma unroll
        for (int j = 0; j < 4; j++) cpa16(dB + j * 16, srcB + j * 4);
        cp_commit();
    };

    copy_tile(0, 0);
    copy_tile(32, 1);

    int st = 0;
#pragma unroll 1
    for (int k0 = 0; k0 < 1024; k0 += 32) {
        if (k0 + 32 < 1024) cp_wait<1>();
        else                cp_wait<0>();
        __syncthreads();
        if (k0 + 64 < 1024) {
            int nst = st + 2; if (nst >= 3) nst -= 3;
            copy_tile(k0 + 64, nst);
        }

        const uint32_t* A  = dynsmem + st * STAGE_WORDS;
        const uint32_t* Bt = A + A_BUF;
#pragma unroll
        for (int kk = 0; kk < 4; kk++) {
            uint32_t af[4][4];
#pragma unroll
            for (int ms = 0; ms < 4; ms++) {
                const uint32_t* ap = A + (wm + 16 * ms + g) * LDA + kk * 8 + 2 * tig;
                uint2 lo = *(const uint2*)ap;
                uint2 hi = *(const uint2*)(ap + 8 * LDA);
                af[ms][0] = lo.x; af[ms][1] = hi.x; af[ms][2] = lo.y; af[ms][3] = hi.y;
            }
#pragma unroll
            for (int nt = 0; nt < 4; nt++) {
                uint2 b = *(const uint2*)(Bt + kk * 1024 + (wn + 8 * nt + g) * 8 + 2 * tig);
#pragma unroll
                for (int ms = 0; ms < 4; ms++)
                    mma8(acc[ms][nt][0], acc[ms][nt][1], acc[ms][nt][2], acc[ms][nt][3],
                         af[ms][0], af[ms][1], af[ms][2], af[ms][3], b.x, b.y);
            }
        }
        st = (st + 1 == 3) ? 0 : st + 1;
    }
}

// ---------------------------------------------------------------------------
// Fused QKV GEMM: [4096,1024] @ [1024,3072]. grid (32, 24), block 256.
// Epilogue writes plain q/k/v [bh][s][d].
// ---------------------------------------------------------------------------
__global__ __launch_bounds__(256, 2) void qkv_kernel(
    const float* __restrict__ bq, const float* __restrict__ bk,
    const float* __restrict__ bv)
{
    const int m0 = blockIdx.x * 128;
    const int n0 = blockIdx.y * 128;

    float acc[4][4][4];
    gemm_main(g_xp + (size_t)m0 * 1024, g_wc + (size_t)n0 * 8, 3072 * 8, acc);

    const int tid  = threadIdx.x;
    const int warp = tid >> 5;
    const int lane = tid & 31;
    const int g    = lane >> 2;
    const int tig  = lane & 3;
    const int wm   = (warp >> 2) * 64;
    const int wn   = (warp & 3) * 32;

#pragma unroll
    for (int ms = 0; ms < 4; ms++) {
#pragma unroll
        for (int nt = 0; nt < 4; nt++) {
            const int r0 = m0 + wm + 16 * ms + g;
            const int r1 = r0 + 8;
            const int C  = n0 + wn + 8 * nt + 2 * tig;
            const int which = C >> 10;
            const int h = (C >> 6) & 15;
            const int d = C & 63;
            const int b  = r0 >> 11;
            const int s0 = r0 & 2047;
            const int s1 = r1 & 2047;
            const int bh = b * 16 + h;

            const float* bp = (which == 0 ? bq : (which == 1 ? bk : bv));
            const float bx = __ldg(&bp[h * 64 + d]);
            const float by = __ldg(&bp[h * 64 + d + 1]);
            float* dst = (which == 0 ? g_q : (which == 1 ? g_kf : g_vf))
                         + (size_t)bh * S_ * 64;
            *(float2*)(dst + (size_t)s0 * 64 + d) =
                make_float2(acc[ms][nt][0] + bx, acc[ms][nt][1] + by);
            *(float2*)(dst + (size_t)s1 * 64 + d) =
                make_float2(acc[ms][nt][2] + bx, acc[ms][nt][3] + by);
        }
    }
}

// ---------------------------------------------------------------------------
// Output projection: [4096,1024] @ [1024,1024]. grid (32, 8), block 256.
// ---------------------------------------------------------------------------
__global__ __launch_bounds__(256, 2) void proj_kernel(
    const float* __restrict__ bo, float* __restrict__ out)
{
    const int m0 = blockIdx.x * 128;
    const int n0 = blockIdx.y * 128;

    float acc[4][4][4];
    gemm_main(g_aop + (size_t)m0 * 1024, g_wop + (size_t)n0 * 8, 1024 * 8, acc);

    const int tid  = threadIdx.x;
    const int warp = tid >> 5;
    const int lane = tid & 31;
    const int g    = lane >> 2;
    const int tig  = lane & 3;
    const int wm   = (warp >> 2) * 64;
    const int wn   = (warp & 3) * 32;

#pragma unroll
    for (int ms = 0; ms < 4; ms++) {
#pragma unroll
        for (int nt = 0; nt < 4; nt++) {
            const int r0 = m0 + wm + 16 * ms + g;
            const int c  = n0 + wn + 8 * nt + 2 * tig;
            const float bx = __ldg(&bo[c]);
            const float by = __ldg(&bo[c + 1]);
            *(float2*)(out + (size_t)r0 * 1024 + c) =
                make_float2(acc[ms][nt][0] + bx, acc[ms][nt][1] + by);
            *(float2*)(out + (size_t)(r0 + 8) * 1024 + c) =
                make_float2(acc[ms][nt][2] + bx, acc[ms][nt][3] + by);
        }
    }
}

// ---------------------------------------------------------------------------
// Flash attention over COMPACTED keys. Block 256 (8 warps), warp = 16 q rows,
// key tiles of 64, cp.async double-buffered K/V. Loop bound = n_pad(b).
// ---------------------------------------------------------------------------
#define LDP 72
#define ATTN_SMEM_WORDS (2*4096 + 2*4096 + 8*16*LDP)
#define ATTN_SMEM_BYTES (ATTN_SMEM_WORDS * 4)

__global__ __launch_bounds__(256) void attn_kernel()
{
    uint32_t* Ks = dynsmem;
    uint32_t* Vs = dynsmem + 2 * 4096;
    uint32_t* Ps = dynsmem + 4 * 4096;

    const int tid  = threadIdx.x;
    const int warp = tid >> 5;
    const int lane = tid & 31;
    const int g    = lane >> 2;
    const int tig  = lane & 3;

    const int bh = blockIdx.y;
    const int b  = bh >> 4;
    const int h  = bh & (H_ - 1);
    const int qbase = blockIdx.x * 128 + warp * 16;

    const int nv   = g_nv[b];
    const int npad = (nv + 63) & ~63;

    const float SC = 0.18033688011112158f;   // (1/8) * log2(e)

    const float* qp = g_q + ((size_t)bh * S_ + qbase) * 64;
    uint32_t qf[8][4];
#pragma unroll
    for (int ks = 0; ks < 8; ks++) {
        const int c0 = ks * 8 + tig;
        qf[ks][0] = f2tf(qp[(size_t)g * 64 + c0]);
        qf[ks][1] = f2tf(qp[(size_t)(g + 8) * 64 + c0]);
        qf[ks][2] = f2tf(qp[(size_t)g * 64 + c0 + 4]);
        qf[ks][3] = f2tf(qp[(size_t)(g + 8) * 64 + c0 + 4]);
    }

    float oacc[8][4];
#pragma unroll
    for (int i = 0; i < 8; i++)
#pragma unroll
        for (int j = 0; j < 4; j++) oacc[i][j] = 0.f;
    float rm0 = -1e30f, rm1 = -1e30f;
    float rl0 = 0.f,    rl1 = 0.f;

    const uint32_t ks_addr = (uint32_t)__cvta_generic_to_shared(Ks);
    const uint32_t vs_addr = (uint32_t)__cvta_generic_to_shared(Vs);
    const uint32_t* kp_base = g_kc + (size_t)bh * 8 * S_ * 8;
    const uint32_t* vp_base = g_vc + (size_t)bh * (S_ / 8) * 512;
    uint32_t* Pw = Ps + warp * 16 * LDP;

    auto copy_kv = [&](int kt, int buf) {
        const uint32_t* srcK = kp_base + (size_t)(tid >> 5) * (S_ * 8)
                               + (size_t)kt * 8 + (tid & 31) * 16;
        uint32_t dK = ks_addr + (uint32_t)buf * 16384 + (uint32_t)(tid >> 5) * 2048
                      + (uint32_t)(tid & 31) * 64;
#pragma unroll
        for (int j = 0; j < 4; j++) cpa16(dK + j * 16, srcK + j * 4);
        const uint32_t* srcV = vp_base + (size_t)kt * 64 + tid * 16;
        uint32_t dV = vs_addr + (uint32_t)buf * 16384 + (uint32_t)tid * 64;
#pragma unroll
        for (int j = 0; j < 4; j++) cpa16(dV + j * 16, srcV + j * 4);
        cp_commit();
    };

    copy_kv(0, 0);

    const float* cm = g_cmask + b * S_;
    int it = 0;
#pragma unroll 1
    for (int kt = 0; kt < npad; kt += 64, it ^= 1) {
        __syncthreads();
        if (kt + 64 < npad) { copy_kv(kt + 64, it ^ 1); cp_wait<1>(); }
        else                { cp_wait<0>(); }
        __syncthreads();

        const uint32_t* Kb = Ks + it * 4096;
        const uint32_t* Vb = Vs + it * 4096;

        float sacc[8][4];
#pragma unroll
        for (int i = 0; i < 8; i++)
#pragma unroll
            for (int j = 0; j < 4; j++) sacc[i][j] = 0.f;
#pragma unroll
        for (int kk = 0; kk < 8; kk++) {
#pragma unroll
            for (int nt = 0; nt < 8; nt++) {
                uint2 bb = *(const uint2*)(Kb + kk * 512 + (nt * 8 + g) * 8 + 2 * tig);
                mma8(sacc[nt][0], sacc[nt][1], sacc[nt][2], sacc[nt][3],
                     qf[kk][0], qf[kk][1], qf[kk][2], qf[kk][3], bb.x, bb.y);
            }
        }

        float tm0 = -1e30f, tm1 = -1e30f;
#pragma unroll
        for (int nt = 0; nt < 8; nt++) {
            const int mc = kt + nt * 8 + 2 * tig;
            const float m0v = __ldg(&cm[mc]);
            const float m1v = __ldg(&cm[mc + 1]);
            sacc[nt][0] = sacc[nt][0] * SC + m0v;
            sacc[nt][1] = sacc[nt][1] * SC + m1v;
            sacc[nt][2] = sacc[nt][2] * SC + m0v;
            sacc[nt][3] = sacc[nt][3] * SC + m1v;
            tm0 = fmaxf(tm0, fmaxf(sacc[nt][0], sacc[nt][1]));
            tm1 = fmaxf(tm1, fmaxf(sacc[nt][2], sacc[nt][3]));
        }
        tm0 = fmaxf(tm0, __shfl_xor_sync(0xffffffff, tm0, 1));
        tm0 = fmaxf(tm0, __shfl_xor_sync(0xffffffff, tm0, 2));
        tm1 = fmaxf(tm1, __shfl_xor_sync(0xffffffff, tm1, 1));
        tm1 = fmaxf(tm1, __shfl_xor_sync(0xffffffff, tm1, 2));

        const float nm0 = fmaxf(rm0, tm0);
        const float nm1 = fmaxf(rm1, tm1);
        const float c0 = exp2f(rm0 - nm0);
        const float c1 = exp2f(rm1 - nm1);
        rm0 = nm0; rm1 = nm1;
        rl0 *= c0;  rl1 *= c1;
#pragma unroll
        for (int nt = 0; nt < 8; nt++) {
            oacc[nt][0] *= c0; oacc[nt][1] *= c0;
            oacc[nt][2] *= c1; oacc[nt][3] *= c1;
        }

#pragma unroll
        for (int nt = 0; nt < 8; nt++) {
            const float p0 = exp2f(sacc[nt][0] - nm0);
            const float p1 = exp2f(sacc[nt][1] - nm0);
            const float p2 = exp2f(sacc[nt][2] - nm1);
            const float p3 = exp2f(sacc[nt][3] - nm1);
            rl0 += p0 + p1;
            rl1 += p2 + p3;
            const int s0 = nt * 8 + tau(2 * tig);
            const int s1 = nt * 8 + tau(2 * tig + 1);
            Pw[g * LDP + s0]       = f2tf(p0);
            Pw[g * LDP + s1]       = f2tf(p1);
            Pw[(g + 8) * LDP + s0] = f2tf(p2);
            Pw[(g + 8) * LDP + s1] = f2tf(p3);
        }
        __syncwarp();

#pragma unroll
        for (int kk = 0; kk < 8; kk++) {
            uint2 alo = *(const uint2*)(Pw + g * LDP + kk * 8 + 2 * tig);
            uint2 ahi = *(const uint2*)(Pw + (g + 8) * LDP + kk * 8 + 2 * tig);
#pragma unroll
            for (int nt = 0; nt < 8; nt++) {
                uint2 bb = *(const uint2*)(Vb + kk * 512 + (nt * 8 + g) * 8 + 2 * tig);
                mma8(oacc[nt][0], oacc[nt][1], oacc[nt][2], oacc[nt][3],
                     alo.x, ahi.x, alo.y, ahi.y, bb.x, bb.y);
            }
        }
    }

    rl0 += __shfl_xor_sync(0xffffffff, rl0, 1);
    rl0 += __shfl_xor_sync(0xffffffff, rl0, 2);
    rl1 += __shfl_xor_sync(0xffffffff, rl1, 1);
    rl1 += __shfl_xor_sync(0xffffffff, rl1, 2);
    const float inv0 = 1.f / rl0;
    const float inv1 = 1.f / rl1;

    const size_t row0 = (size_t)b * S_ + qbase + g;
#pragma unroll
    for (int nt = 0; nt < 8; nt++) {
        const int C  = h * 64 + nt * 8 + 2 * tig;
        const int w0 = (C & ~7) + tau(C & 7);
        const int w1 = (C & ~7) + tau((C + 1) & 7);
        g_aop[row0 * 1024 + w0]       = f2tf(oacc[nt][0] * inv0);
        g_aop[row0 * 1024 + w1]       = f2tf(oacc[nt][1] * inv0);
        g_aop[(row0 + 8) * 1024 + w0] = f2tf(oacc[nt][2] * inv1);
        g_aop[(row0 + 8) * 1024 + w1] = f2tf(oacc[nt][3] * inv1);
    }
}

// ---------------------------------------------------------------------------
extern "C" void kernel_launch(void* const* d_in, const int* in_sizes, int n_in,
                              void* d_out, int out_size)
{
    const float* x    = (const float*)d_in[0];
    const int*   mask = (const int*)  d_in[1];
    const float* wq   = (const float*)d_in[2];
    const float* bq   = (const float*)d_in[3];
    const float* wk   = (const float*)d_in[4];
    const float* bk   = (const float*)d_in[5];
    const float* wv   = (const float*)d_in[6];
    const float* bv   = (const float*)d_in[7];
    const float* wo   = (const float*)d_in[8];
    const float* bo   = (const float*)d_in[9];
    float* out = (float*)d_out;

    static bool attrs_set = false;
    if (!attrs_set) {
        cudaFuncSetAttribute(qkv_kernel,  cudaFuncAttributeMaxDynamicSharedMemorySize, GEMM_SMEM_BYTES);
        cudaFuncSetAttribute(proj_kernel, cudaFuncAttributeMaxDynamicSharedMemorySize, GEMM_SMEM_BYTES);
        cudaFuncSetAttribute(attn_kernel, cudaFuncAttributeMaxDynamicSharedMemorySize, ATTN_SMEM_BYTES);
        attrs_set = true;
    }

    prep_x <<<(B_ * S_ * E_ / 8) / 256, 256>>>(x);
    prep_wc<<<128 * 12, 256>>>(wq, wk, wv);
    prep_wo<<<128 * 4, 256>>>(wo);
    scan_mask<<<B_, 1024>>>(mask);

    dim3 g1(S_ * B_ / 128, 3072 / 128);
    qkv_kernel<<<g1, 256, GEMM_SMEM_BYTES>>>(bq, bk, bv);

    dim3 gc(S_ / 8, BH_);
    compact_kv<<<gc, 64>>>();

    dim3 g2(S_ / 128, BH_);
    attn_kernel<<<g2, 256, ATTN_SMEM_BYTES>>>();

    dim3 g3((B_ * S_) / 128, E_ / 128);
    proj_kernel<<<g3, 256, GEMM_SMEM_BYTES>>>(bo, out);
}

// round 6
// speedup vs baseline: 2.9437x; 2.0166x over previous
#include <cuda_runtime.h>
#include <cuda_fp16.h>
#include <math.h>
#include <stdint.h>

#define B_  2
#define S_  2048
#define E_  1024
#define H_  16
#define DH_ 64
#define BH_ (B_*H_)

// ---------------------------------------------------------------------------
// Global scratch (allocation-free rule)
// ---------------------------------------------------------------------------
__device__ __half    g_xh [(size_t)B_*S_*E_];           // x fp16, 16k-permuted [4096][1024]
__device__ uint32_t  g_wch[(size_t)64*3072*8];          // QKV W frag: [k16][n][8 words]
__device__ uint32_t  g_woh[(size_t)64*1024*8];          // wo frag:    [k16][n][8 words]
__device__ __half    g_qh [(size_t)BH_*S_*DH_];         // plain [bh][S][64]
__device__ __half    g_kh [(size_t)BH_*S_*DH_];
__device__ __half    g_vh [(size_t)BH_*S_*DH_];
__device__ uint32_t  g_kc [(size_t)BH_*4*S_*8];         // compact K frag [bh][d16][key][8w]
__device__ uint32_t  g_vc [(size_t)BH_*(S_/16)*DH_*8];  // compact V frag [bh][k16][d][8w]
__device__ uint32_t  g_aoh[(size_t)B_*S_*512];          // attn out fp16 perm [4096][512w]
__device__ int       g_perm[(size_t)B_*S_];
__device__ int       g_nv[B_];
__device__ float     g_cmask[(size_t)B_*S_];            // 0 or -1e9*log2e

// ---------------------------------------------------------------------------
// helpers
// ---------------------------------------------------------------------------
__device__ __forceinline__ int posf(int j) {            // 16-k block permutation
    return ((j & 6) + (j >> 3)) * 2 + (j & 1);
}

__device__ __forceinline__ void mma16(float& d0, float& d1, float& d2, float& d3,
                                      uint32_t a0, uint32_t a1, uint32_t a2, uint32_t a3,
                                      uint32_t b0, uint32_t b1) {
    asm volatile(
        "mma.sync.aligned.m16n8k16.row.col.f32.f16.f16.f32 "
        "{%0,%1,%2,%3}, {%4,%5,%6,%7}, {%8,%9}, {%0,%1,%2,%3};"
        : "+f"(d0), "+f"(d1), "+f"(d2), "+f"(d3)
        : "r"(a0), "r"(a1), "r"(a2), "r"(a3), "r"(b0), "r"(b1));
}

__device__ __forceinline__ void cpa16(uint32_t dst_smem, const void* src) {
    asm volatile("cp.async.cg.shared.global [%0], [%1], 16;\n"
                 :: "r"(dst_smem), "l"(src));
}
__device__ __forceinline__ void cp_commit() {
    asm volatile("cp.async.commit_group;\n");
}
template<int N> __device__ __forceinline__ void cp_wait() {
    asm volatile("cp.async.wait_group %0;\n" :: "n"(N));
}

__device__ __forceinline__ uint32_t h2u(__half2 h) {
    return *reinterpret_cast<uint32_t*>(&h);
}

// ---------------------------------------------------------------------------
// prep kernels
// ---------------------------------------------------------------------------
__global__ __launch_bounds__(256) void prep_x(const float* __restrict__ x) {
    int i = blockIdx.x * 256 + threadIdx.x;      // cell per 16-col group
    int row = i >> 6, grp = i & 63;
    const float* s = x + (size_t)row * 1024 + grp * 16;
    float v[16];
#pragma unroll
    for (int j = 0; j < 4; j++) {
        float4 t = *(const float4*)(s + j * 4);
        v[j*4] = t.x; v[j*4+1] = t.y; v[j*4+2] = t.z; v[j*4+3] = t.w;
    }
    __align__(16) __half o[16];
#pragma unroll
    for (int j = 0; j < 16; j++) o[posf(j)] = __float2half_rn(v[j]);
    *(uint4*)(g_xh + (size_t)row * 1024 + grp * 16)     = ((uint4*)o)[0];
    *(uint4*)(g_xh + (size_t)row * 1024 + grp * 16 + 8) = ((uint4*)o)[1];
}

// combined QKV weight: col n: which=n>>10, h=(n>>6)&15, d=n&63
__global__ __launch_bounds__(256) void prep_wc(const float* __restrict__ wq,
                                               const float* __restrict__ wk,
                                               const float* __restrict__ wv) {
    int i = blockIdx.x * 256 + threadIdx.x;      // 64*3072 cells
    int k16 = i >> 12;                           // 0..63 (i/4096? no) -- fix below
    // i = k16*3072 + n
    k16 = i / 3072;
    int n = i - k16 * 3072;
    int which = n >> 10;
    int h = (n >> 6) & 15;
    int d = n & 63;
    const float* w = (which == 0 ? wq : (which == 1 ? wk : wv))
                     + ((size_t)h * 1024 + k16 * 16) * 64 + d;
    __align__(16) __half o[16];
#pragma unroll
    for (int j = 0; j < 16; j++) o[posf(j)] = __float2half_rn(w[j * 64]);
    uint32_t* dst = g_wch + ((size_t)k16 * 3072 + n) * 8;
    *(uint4*)dst       = ((uint4*)o)[0];
    *(uint4*)(dst + 4) = ((uint4*)o)[1];
}

__global__ __launch_bounds__(256) void prep_wo(const float* __restrict__ wo) {
    int i = blockIdx.x * 256 + threadIdx.x;      // 64*1024 cells
    int k16 = i >> 10;
    int n = i & 1023;
    __align__(16) __half o[16];
#pragma unroll
    for (int j = 0; j < 16; j++)
        o[posf(j)] = __float2half_rn(wo[(size_t)(k16 * 16 + j) * 1024 + n]);
    uint32_t* dst = g_woh + ((size_t)k16 * 1024 + n) * 8;
    *(uint4*)dst       = ((uint4*)o)[0];
    *(uint4*)(dst + 4) = ((uint4*)o)[1];
}

// ---------------------------------------------------------------------------
// Mask scan
// ---------------------------------------------------------------------------
__global__ __launch_bounds__(1024) void scan_mask(const int* __restrict__ mask) {
    __shared__ int buf[2][1024];
    const int b = blockIdx.x, t = threadIdx.x;
    const int m0 = mask[b * 2048 + 2 * t]     != 0;
    const int m1 = mask[b * 2048 + 2 * t + 1] != 0;
    const int sum = m0 + m1;
    buf[0][t] = sum;
    __syncthreads();
    int src = 0;
    for (int off = 1; off < 1024; off <<= 1) {
        int v = buf[src][t];
        if (t >= off) v += buf[src][t - off];
        buf[src ^ 1][t] = v;
        src ^= 1;
        __syncthreads();
    }
    const int incl = buf[src][t];
    const int nv   = buf[src][1023];
    const int excl = incl - sum;
    if (m0) g_perm[b * 2048 + excl]      = 2 * t;
    if (m1) g_perm[b * 2048 + excl + m0] = 2 * t + 1;
    if (t == 0) g_nv[b] = nv;
    const float MBv = -1.4426950408889634e9f;
    g_cmask[b * 2048 + 2 * t]     = (2 * t     < nv) ? 0.f : MBv;
    g_cmask[b * 2048 + 2 * t + 1] = (2 * t + 1 < nv) ? 0.f : MBv;
}

// ---------------------------------------------------------------------------
// Compact + convert K/V into fp16 fragment layouts.
// grid (S/16, BH), block 64.
// ---------------------------------------------------------------------------
__global__ __launch_bounds__(64) void compact_kv() {
    const int bh = blockIdx.y;
    const int b  = bh >> 4;
    const int jg = blockIdx.x;            // group of 16 keys
    const int nv   = g_nv[b];
    const int npad = (nv + 63) & ~63;
    if (jg * 16 >= npad) return;

    __shared__ int sidx[16];
    __shared__ __half sk[16][64];
    const int t = threadIdx.x;
    if (t < 16) {
        const int j = jg * 16 + t;
        sidx[t] = (j < nv) ? g_perm[b * 2048 + j] : -1;
    }
    __syncthreads();

    const __half* kh = g_kh + (size_t)bh * S_ * 64;
    const __half* vh = g_vh + (size_t)bh * S_ * 64;
    const __half hz = __float2half_rn(0.f);

#pragma unroll
    for (int j = 0; j < 16; j++)
        sk[j][t] = (sidx[j] >= 0) ? kh[(size_t)sidx[j] * 64 + t] : hz;
    __syncthreads();

    // K frag: thread = (blk, key); cell = ((bh*4+blk)*S + jg*16+key)*8 words
    {
        const int blk = t >> 4, key = t & 15;
        __align__(16) __half o[16];
#pragma unroll
        for (int j = 0; j < 16; j++) o[posf(j)] = sk[key][blk * 16 + j];
        uint32_t* dst = g_kc + ((size_t)(bh * 4 + blk) * S_ + jg * 16 + key) * 8;
        *(uint4*)dst       = ((uint4*)o)[0];
        *(uint4*)(dst + 4) = ((uint4*)o)[1];
    }

    // V frag: thread = d; cell = ((bh*(S/16)+jg)*64 + d)*8 words
    {
        __align__(16) __half o[16];
#pragma unroll
        for (int j = 0; j < 16; j++)
            o[posf(j)] = (sidx[j] >= 0) ? vh[(size_t)sidx[j] * 64 + t] : hz;
        uint32_t* dst = g_vc + (((size_t)bh * (S_ / 16) + jg) * 64 + t) * 8;
        *(uint4*)dst       = ((uint4*)o)[0];
        *(uint4*)(dst + 4) = ((uint4*)o)[1];
    }
}

// ---------------------------------------------------------------------------
// GEMM mainloop (fp16): 128x128 tile, 256 threads (8 warps, warp tile 64x32),
// k-step 32 halves, 4-stage cp.async ring.
// ---------------------------------------------------------------------------
#define LDA 24                          // words per A row (16 content + 8 pad)
#define A_BUF (128*LDA)                 // 3072 words
#define B_BUF 2048                      // 2 k16 x 128 n x 8 words
#define STAGE_WORDS (A_BUF + B_BUF)     // 5120 words = 20KB
#define GEMM_SMEM_BYTES (4 * STAGE_WORDS * 4)

extern __shared__ uint32_t dynsmem[];

__device__ __forceinline__ void gemm_main(
    const __half* __restrict__ Ah,       // row length 1024 halves
    const uint32_t* __restrict__ Bw,     // [k16][nTot][8w] + n0*8
    int nTot,
    float acc[4][4][4])
{
    const int tid  = threadIdx.x;
    const int warp = tid >> 5;
    const int lane = tid & 31;
    const int g    = lane >> 2;
    const int tig  = lane & 3;
    const int wm   = (warp >> 2) * 64;
    const int wn   = (warp & 3) * 32;

#pragma unroll
    for (int ms = 0; ms < 4; ms++)
#pragma unroll
        for (int nt = 0; nt < 4; nt++)
#pragma unroll
            for (int r = 0; r < 4; r++) acc[ms][nt][r] = 0.f;

    const uint32_t sm = (uint32_t)__cvta_generic_to_shared(dynsmem);

    const int arow = tid >> 1;
    const int apart = tid & 1;
    const int bblk = tid >> 7;           // 0..1
    const int bn   = tid & 127;

    auto copy_tile = [&](int k0, int st) {   // k0 in halves
        const uint32_t base = sm + (uint32_t)st * (STAGE_WORDS * 4);
        uint32_t dA = base + (uint32_t)arow * (LDA * 4) + (uint32_t)apart * 32;
        const __half* srcA = Ah + (size_t)arow * 1024 + k0 + apart * 16;
        cpa16(dA, srcA);
        cpa16(dA + 16, srcA + 8);
        uint32_t dB = base + A_BUF * 4 + (uint32_t)(bblk * 1024 + bn * 8) * 4;
        const uint32_t* srcB = Bw + ((size_t)((k0 >> 4) + bblk) * nTot + bn) * 8;
        cpa16(dB, srcB);
        cpa16(dB + 16, srcB + 4);
        cp_commit();
    };

    copy_tile(0, 0);
    copy_tile(32, 1);
    copy_tile(64, 2);

    int st = 0;
#pragma unroll 1
    for (int k0 = 0; k0 < 1024; k0 += 32) {
        if (k0 + 64 < 1024)      cp_wait<2>();
        else if (k0 + 32 < 1024) cp_wait<1>();
        else                     cp_wait<0>();
        __syncthreads();
        if (k0 + 96 < 1024) {
            int nst = st + 3; if (nst >= 4) nst -= 4;
            copy_tile(k0 + 96, nst);
        }

        const uint32_t* A  = dynsmem + st * STAGE_WORDS;
        const uint32_t* Bt = A + A_BUF;
#pragma unroll
        for (int kk = 0; kk < 2; kk++) {
            uint32_t af[4][4];
#pragma unroll
            for (int ms = 0; ms < 4; ms++) {
                const uint32_t* ap = A + (wm + 16 * ms + g) * LDA + kk * 8 + 2 * tig;
                uint2 lo = *(const uint2*)ap;              // row g:   a0, a2
                uint2 hi = *(const uint2*)(ap + 8 * LDA);  // row g+8: a1, a3
                af[ms][0] = lo.x; af[ms][1] = hi.x; af[ms][2] = lo.y; af[ms][3] = hi.y;
            }
#pragma unroll
            for (int nt = 0; nt < 4; nt++) {
                uint2 b = *(const uint2*)(Bt + kk * 1024 + (wn + 8 * nt + g) * 8 + 2 * tig);
#pragma unroll
                for (int ms = 0; ms < 4; ms++)
                    mma16(acc[ms][nt][0], acc[ms][nt][1], acc[ms][nt][2], acc[ms][nt][3],
                          af[ms][0], af[ms][1], af[ms][2], af[ms][3], b.x, b.y);
            }
        }
        st = (st + 1 == 4) ? 0 : st + 1;
    }
}

// ---------------------------------------------------------------------------
// Fused QKV GEMM: [4096,1024] @ [1024,3072]. grid (32, 24), block 256.
// ---------------------------------------------------------------------------
__global__ __launch_bounds__(256, 2) void qkv_kernel(
    const float* __restrict__ bq, const float* __restrict__ bk,
    const float* __restrict__ bv)
{
    const int m0 = blockIdx.x * 128;
    const int n0 = blockIdx.y * 128;

    float acc[4][4][4];
    gemm_main(g_xh + (size_t)m0 * 1024, g_wch + (size_t)n0 * 8, 3072, acc);

    const int tid  = threadIdx.x;
    const int warp = tid >> 5;
    const int lane = tid & 31;
    const int g    = lane >> 2;
    const int tig  = lane & 3;
    const int wm   = (warp >> 2) * 64;
    const int wn   = (warp & 3) * 32;

#pragma unroll
    for (int ms = 0; ms < 4; ms++) {
#pragma unroll
        for (int nt = 0; nt < 4; nt++) {
            const int r0 = m0 + wm + 16 * ms + g;
            const int r1 = r0 + 8;
            const int C  = n0 + wn + 8 * nt + 2 * tig;
            const int which = C >> 10;
            const int h = (C >> 6) & 15;
            const int d = C & 63;
            const int b  = r0 >> 11;
            const int s0 = r0 & 2047;
            const int s1 = r1 & 2047;
            const int bh = b * 16 + h;

            const float* bp = (which == 0 ? bq : (which == 1 ? bk : bv));
            const float bx = __ldg(&bp[h * 64 + d]);
            const float by = __ldg(&bp[h * 64 + d + 1]);
            __half* dst = (which == 0 ? g_qh : (which == 1 ? g_kh : g_vh))
                          + (size_t)bh * S_ * 64;
            *(__half2*)(dst + (size_t)s0 * 64 + d) =
                __floats2half2_rn(acc[ms][nt][0] + bx, acc[ms][nt][1] + by);
            *(__half2*)(dst + (size_t)s1 * 64 + d) =
                __floats2half2_rn(acc[ms][nt][2] + bx, acc[ms][nt][3] + by);
        }
    }
}

// ---------------------------------------------------------------------------
// Output projection: [4096,1024] @ [1024,1024]. grid (32, 8), block 256.
// ---------------------------------------------------------------------------
__global__ __launch_bounds__(256, 2) void proj_kernel(
    const float* __restrict__ bo, float* __restrict__ out)
{
    const int m0 = blockIdx.x * 128;
    const int n0 = blockIdx.y * 128;

    float acc[4][4][4];
    gemm_main((const __half*)g_aoh + (size_t)m0 * 1024, g_woh + (size_t)n0 * 8,
              1024, acc);

    const int tid  = threadIdx.x;
    const int warp = tid >> 5;
    const int lane = tid & 31;
    const int g    = lane >> 2;
    const int tig  = lane & 3;
    const int wm   = (warp >> 2) * 64;
    const int wn   = (warp & 3) * 32;

#pragma unroll
    for (int ms = 0; ms < 4; ms++) {
#pragma unroll
        for (int nt = 0; nt < 4; nt++) {
            const int r0 = m0 + wm + 16 * ms + g;
            const int c  = n0 + wn + 8 * nt + 2 * tig;
            const float bx = __ldg(&bo[c]);
            const float by = __ldg(&bo[c + 1]);
            *(float2*)(out + (size_t)r0 * 1024 + c) =
                make_float2(acc[ms][nt][0] + bx, acc[ms][nt][1] + by);
            *(float2*)(out + (size_t)(r0 + 8) * 1024 + c) =
                make_float2(acc[ms][nt][2] + bx, acc[ms][nt][3] + by);
        }
    }
}

// ---------------------------------------------------------------------------
// Flash attention (fp16 MMA) over compacted keys.
// Block 256 (8 warps), warp = 16 q rows, key tiles of 64.
// SMEM: K 2x2048w, V 2x2048w, P 8x16xLDP
// ---------------------------------------------------------------------------
#define LDP 40
#define ATTN_SMEM_WORDS (2*2048 + 2*2048 + 8*16*LDP)
#define ATTN_SMEM_BYTES (ATTN_SMEM_WORDS * 4)

__global__ __launch_bounds__(256) void attn_kernel()
{
    uint32_t* Ks = dynsmem;
    uint32_t* Vs = dynsmem + 2 * 2048;
    uint32_t* Ps = dynsmem + 4 * 2048;

    const int tid  = threadIdx.x;
    const int warp = tid >> 5;
    const int lane = tid & 31;
    const int g    = lane >> 2;
    const int tig  = lane & 3;

    const int bh = blockIdx.y;
    const int b  = bh >> 4;
    const int h  = bh & (H_ - 1);
    const int qbase = blockIdx.x * 128 + warp * 16;

    const int nv   = g_nv[b];
    const int npad = (nv + 63) & ~63;

    const float SC = 0.18033688011112158f;   // (1/8) * log2(e)

    // Q A-fragments: 4 k16-blocks, 4 regs each
    const __half* qp = g_qh + ((size_t)bh * S_ + qbase) * 64;
    uint32_t qf[4][4];
#pragma unroll
    for (int kk = 0; kk < 4; kk++) {
        qf[kk][0] = *(const uint32_t*)(qp + (size_t)g * 64 + kk * 16 + 2 * tig);
        qf[kk][1] = *(const uint32_t*)(qp + (size_t)(g + 8) * 64 + kk * 16 + 2 * tig);
        qf[kk][2] = *(const uint32_t*)(qp + (size_t)g * 64 + kk * 16 + 8 + 2 * tig);
        qf[kk][3] = *(const uint32_t*)(qp + (size_t)(g + 8) * 64 + kk * 16 + 8 + 2 * tig);
    }

    float oacc[8][4];
#pragma unroll
    for (int i = 0; i < 8; i++)
#pragma unroll
        for (int j = 0; j < 4; j++) oacc[i][j] = 0.f;
    float rm0 = -1e30f, rm1 = -1e30f;
    float rl0 = 0.f,    rl1 = 0.f;

    const uint32_t ks_addr = (uint32_t)__cvta_generic_to_shared(Ks);
    const uint32_t vs_addr = (uint32_t)__cvta_generic_to_shared(Vs);
    const uint32_t* kc_base = g_kc + (size_t)bh * 4 * S_ * 8;
    const uint32_t* vc_base = g_vc + (size_t)bh * (S_ / 16) * 512;
    uint32_t* Pw = Ps + warp * 16 * LDP;

    // NOTE: Q frags were loaded from permuted?? g_qh is PLAIN layout; A-frag
    // needs halves (2tig,2tig+1) and (2tig+8,2tig+9) within each k16 block —
    // plain layout gives exactly that at cols kk*16+2tig and kk*16+8+2tig. OK.

    auto copy_kv = [&](int kt, int buf) {
        // K tile: [blk d16][key 0..63][8w]
        const int blk = tid >> 6, kx = tid & 63;
        const uint32_t* srcK = kc_base + ((size_t)blk * S_ + kt + kx) * 8;
        uint32_t dK = ks_addr + (uint32_t)buf * 8192
                      + (uint32_t)(blk * 512 + kx * 8) * 4;
        cpa16(dK, srcK);
        cpa16(dK + 16, srcK + 4);
        // V tile: [blk k16][d 0..63][8w]
        const uint32_t* srcV = vc_base + (((size_t)(kt >> 4) + blk) * 64 + kx) * 8;
        uint32_t dV = vs_addr + (uint32_t)buf * 8192
                      + (uint32_t)(blk * 512 + kx * 8) * 4;
        cpa16(dV, srcV);
        cpa16(dV + 16, srcV + 4);
        cp_commit();
    };

    copy_kv(0, 0);

    const float* cm = g_cmask + b * S_;
    int it = 0;
#pragma unroll 1
    for (int kt = 0; kt < npad; kt += 64, it ^= 1) {
        __syncthreads();
        if (kt + 64 < npad) { copy_kv(kt + 64, it ^ 1); cp_wait<1>(); }
        else                { cp_wait<0>(); }
        __syncthreads();

        const uint32_t* Kb = Ks + it * 2048;
        const uint32_t* Vb = Vs + it * 2048;

        // scores = Q @ K^T
        float sacc[8][4];
#pragma unroll
        for (int i = 0; i < 8; i++)
#pragma unroll
            for (int j = 0; j < 4; j++) sacc[i][j] = 0.f;
#pragma unroll
        for (int kk = 0; kk < 4; kk++) {
#pragma unroll
            for (int nt = 0; nt < 8; nt++) {
                uint2 bb = *(const uint2*)(Kb + kk * 512 + (nt * 8 + g) * 8 + 2 * tig);
                mma16(sacc[nt][0], sacc[nt][1], sacc[nt][2], sacc[nt][3],
                      qf[kk][0], qf[kk][1], qf[kk][2], qf[kk][3], bb.x, bb.y);
            }
        }

        // scale + mask + tile row-max (exp2 domain)
        float tm0 = -1e30f, tm1 = -1e30f;
#pragma unroll
        for (int nt = 0; nt < 8; nt++) {
            const int mc = kt + nt * 8 + 2 * tig;
            const float m0v = __ldg(&cm[mc]);
            const float m1v = __ldg(&cm[mc + 1]);
            sacc[nt][0] = sacc[nt][0] * SC + m0v;
            sacc[nt][1] = sacc[nt][1] * SC + m1v;
            sacc[nt][2] = sacc[nt][2] * SC + m0v;
            sacc[nt][3] = sacc[nt][3] * SC + m1v;
            tm0 = fmaxf(tm0, fmaxf(sacc[nt][0], sacc[nt][1]));
            tm1 = fmaxf(tm1, fmaxf(sacc[nt][2], sacc[nt][3]));
        }
        tm0 = fmaxf(tm0, __shfl_xor_sync(0xffffffff, tm0, 1));
        tm0 = fmaxf(tm0, __shfl_xor_sync(0xffffffff, tm0, 2));
        tm1 = fmaxf(tm1, __shfl_xor_sync(0xffffffff, tm1, 1));
        tm1 = fmaxf(tm1, __shfl_xor_sync(0xffffffff, tm1, 2));

        const float nm0 = fmaxf(rm0, tm0);
        const float nm1 = fmaxf(rm1, tm1);
        const float c0 = exp2f(rm0 - nm0);
        const float c1 = exp2f(rm1 - nm1);
        rm0 = nm0; rm1 = nm1;
        rl0 *= c0;  rl1 *= c1;
#pragma unroll
        for (int nt = 0; nt < 8; nt++) {
            oacc[nt][0] *= c0; oacc[nt][1] *= c0;
            oacc[nt][2] *= c1; oacc[nt][3] *= c1;
        }

        // P = exp2(s - m), stage to SMEM in permuted fp16 layout
#pragma unroll
        for (int nt = 0; nt < 8; nt++) {
            const float p0 = exp2f(sacc[nt][0] - nm0);
            const float p1 = exp2f(sacc[nt][1] - nm0);
            const float p2 = exp2f(sacc[nt][2] - nm1);
            const float p3 = exp2f(sacc[nt][3] - nm1);
            rl0 += p0 + p1;
            rl1 += p2 + p3;
            const int c = nt * 8 + 2 * tig;
            const int j = c & 15;
            const int w = (c >> 4) * 8 + (j & 6) + (j >> 3);
            Pw[g * LDP + w]       = h2u(__floats2half2_rn(p0, p1));
            Pw[(g + 8) * LDP + w] = h2u(__floats2half2_rn(p2, p3));
        }
        __syncwarp();

        // O += P @ V
#pragma unroll
        for (int kk = 0; kk < 4; kk++) {
            uint2 alo = *(const uint2*)(Pw + g * LDP + kk * 8 + 2 * tig);
            uint2 ahi = *(const uint2*)(Pw + (g + 8) * LDP + kk * 8 + 2 * tig);
#pragma unroll
            for (int nt = 0; nt < 8; nt++) {
                uint2 bb = *(const uint2*)(Vb + kk * 512 + (nt * 8 + g) * 8 + 2 * tig);
                mma16(oacc[nt][0], oacc[nt][1], oacc[nt][2], oacc[nt][3],
                      alo.x, ahi.x, alo.y, ahi.y, bb.x, bb.y);
            }
        }
    }

    rl0 += __shfl_xor_sync(0xffffffff, rl0, 1);
    rl0 += __shfl_xor_sync(0xffffffff, rl0, 2);
    rl1 += __shfl_xor_sync(0xffffffff, rl1, 1);
    rl1 += __shfl_xor_sync(0xffffffff, rl1, 2);
    const float inv0 = 1.f / rl0;
    const float inv1 = 1.f / rl1;

    // write attention output in permuted fp16 layout for proj (row = 512 words)
    const size_t row0 = (size_t)b * S_ + qbase + g;
#pragma unroll
    for (int nt = 0; nt < 8; nt++) {
        const int C = h * 64 + nt * 8 + 2 * tig;
        const int j = C & 15;
        const int w = (C >> 4) * 8 + (j & 6) + (j >> 3);
        g_aoh[row0 * 512 + w] =
            h2u(__floats2half2_rn(oacc[nt][0] * inv0, oacc[nt][1] * inv0));
        g_aoh[(row0 + 8) * 512 + w] =
            h2u(__floats2half2_rn(oacc[nt][2] * inv1, oacc[nt][3] * inv1));
    }
}

// ---------------------------------------------------------------------------
extern "C" void kernel_launch(void* const* d_in, const int* in_sizes, int n_in,
                              void* d_out, int out_size)
{
    const float* x    = (const float*)d_in[0];
    const int*   mask = (const int*)  d_in[1];
    const float* wq   = (const float*)d_in[2];
    const float* bq   = (const float*)d_in[3];
    const float* wk   = (const float*)d_in[4];
    const float* bk   = (const float*)d_in[5];
    const float* wv   = (const float*)d_in[6];
    const float* bv   = (const float*)d_in[7];
    const float* wo   = (const float*)d_in[8];
    const float* bo   = (const float*)d_in[9];
    float* out = (float*)d_out;

    static bool attrs_set = false;
    if (!attrs_set) {
        cudaFuncSetAttribute(qkv_kernel,  cudaFuncAttributeMaxDynamicSharedMemorySize, GEMM_SMEM_BYTES);
        cudaFuncSetAttribute(proj_kernel, cudaFuncAttributeMaxDynamicSharedMemorySize, GEMM_SMEM_BYTES);
        cudaFuncSetAttribute(attn_kernel, cudaFuncAttributeMaxDynamicSharedMemorySize, ATTN_SMEM_BYTES);
        attrs_set = true;
    }

    prep_x <<<(B_ * S_ * 64) / 256, 256>>>(x);          // 4096*64 cells
    prep_wc<<<(64 * 3072) / 256, 256>>>(wq, wk, wv);
    prep_wo<<<(64 * 1024) / 256, 256>>>(wo);
    scan_mask<<<B_, 1024>>>(mask);

    dim3 g1(S_ * B_ / 128, 3072 / 128);
    qkv_kernel<<<g1, 256, GEMM_SMEM_BYTES>>>(bq, bk, bv);

    dim3 gc(S_ / 16, BH_);
    compact_kv<<<gc, 64>>>();

    dim3 g2(S_ / 128, BH_);
    attn_kernel<<<g2, 256, ATTN_SMEM_BYTES>>>();

    dim3 g3((B_ * S_) / 128, E_ / 128);
    proj_kernel<<<g3, 256, GEMM_SMEM_BYTES>>>(bo, out);
}

// round 7
// speedup vs baseline: 2.9865x; 1.0145x over previous
#include <cuda_runtime.h>
#include <cuda_fp16.h>
#include <math.h>
#include <stdint.h>

#define B_  2
#define S_  2048
#define E_  1024
#define H_  16
#define DH_ 64
#define BH_ (B_*H_)

// ---------------------------------------------------------------------------
// Global scratch (allocation-free rule)
// ---------------------------------------------------------------------------
__device__ __half    g_xh [(size_t)B_*S_*E_];           // x fp16, 16k-permuted [4096][1024]
__device__ uint32_t  g_wch[(size_t)64*3072*8];          // QKV W frag: [k16][n][8 words]
__device__ uint32_t  g_woh[(size_t)64*1024*8];          // wo frag:    [k16][n][8 words]
__device__ __half    g_qh [(size_t)BH_*S_*DH_];         // plain [bh][S][64], pre-scaled
__device__ __half    g_kh [(size_t)BH_*S_*DH_];
__device__ __half    g_vh [(size_t)BH_*S_*DH_];
__device__ uint32_t  g_kc [(size_t)BH_*4*S_*8];         // compact K frag [bh][d16][key][8w]
__device__ uint32_t  g_vc [(size_t)BH_*(S_/16)*DH_*8];  // compact V frag [bh][k16][d][8w]
__device__ uint32_t  g_aoh[(size_t)B_*S_*512];          // attn out fp16 perm [4096][512w]
__device__ int       g_perm[(size_t)B_*S_];
__device__ int       g_nv[B_];
__device__ float     g_cmask[(size_t)B_*S_];            // 0 or -1e9*log2e

// ---------------------------------------------------------------------------
// helpers
// ---------------------------------------------------------------------------
__device__ __forceinline__ int posf(int j) {            // 16-k block permutation
    return ((j & 6) + (j >> 3)) * 2 + (j & 1);
}

__device__ __forceinline__ void mma16(float& d0, float& d1, float& d2, float& d3,
                                      uint32_t a0, uint32_t a1, uint32_t a2, uint32_t a3,
                                      uint32_t b0, uint32_t b1) {
    asm volatile(
        "mma.sync.aligned.m16n8k16.row.col.f32.f16.f16.f32 "
        "{%0,%1,%2,%3}, {%4,%5,%6,%7}, {%8,%9}, {%0,%1,%2,%3};"
        : "+f"(d0), "+f"(d1), "+f"(d2), "+f"(d3)
        : "r"(a0), "r"(a1), "r"(a2), "r"(a3), "r"(b0), "r"(b1));
}

__device__ __forceinline__ void cpa16(uint32_t dst_smem, const void* src) {
    asm volatile("cp.async.cg.shared.global [%0], [%1], 16;\n"
                 :: "r"(dst_smem), "l"(src));
}
__device__ __forceinline__ void cp_commit() {
    asm volatile("cp.async.commit_group;\n");
}
template<int N> __device__ __forceinline__ void cp_wait() {
    asm volatile("cp.async.wait_group %0;\n" :: "n"(N));
}

__device__ __forceinline__ uint32_t h2u(__half2 h) {
    return *reinterpret_cast<uint32_t*>(&h);
}

// ---------------------------------------------------------------------------
// prep kernels
// ---------------------------------------------------------------------------
__global__ __launch_bounds__(256) void prep_x(const float* __restrict__ x) {
    int i = blockIdx.x * 256 + threadIdx.x;      // cell per 16-col group
    int row = i >> 6, grp = i & 63;
    const float* s = x + (size_t)row * 1024 + grp * 16;
    float v[16];
#pragma unroll
    for (int j = 0; j < 4; j++) {
        float4 t = *(const float4*)(s + j * 4);
        v[j*4] = t.x; v[j*4+1] = t.y; v[j*4+2] = t.z; v[j*4+3] = t.w;
    }
    __align__(16) __half o[16];
#pragma unroll
    for (int j = 0; j < 16; j++) o[posf(j)] = __float2half_rn(v[j]);
    *(uint4*)(g_xh + (size_t)row * 1024 + grp * 16)     = ((uint4*)o)[0];
    *(uint4*)(g_xh + (size_t)row * 1024 + grp * 16 + 8) = ((uint4*)o)[1];
}

// combined QKV weight: col n: which=n>>10, h=(n>>6)&15, d=n&63
__global__ __launch_bounds__(256) void prep_wc(const float* __restrict__ wq,
                                               const float* __restrict__ wk,
                                               const float* __restrict__ wv) {
    int i = blockIdx.x * 256 + threadIdx.x;      // 64*3072 cells: i = k16*3072 + n
    int k16 = i / 3072;
    int n = i - k16 * 3072;
    int which = n >> 10;
    int h = (n >> 6) & 15;
    int d = n & 63;
    const float* w = (which == 0 ? wq : (which == 1 ? wk : wv))
                     + ((size_t)h * 1024 + k16 * 16) * 64 + d;
    __align__(16) __half o[16];
#pragma unroll
    for (int j = 0; j < 16; j++) o[posf(j)] = __float2half_rn(w[j * 64]);
    uint32_t* dst = g_wch + ((size_t)k16 * 3072 + n) * 8;
    *(uint4*)dst       = ((uint4*)o)[0];
    *(uint4*)(dst + 4) = ((uint4*)o)[1];
}

__global__ __launch_bounds__(256) void prep_wo(const float* __restrict__ wo) {
    int i = blockIdx.x * 256 + threadIdx.x;      // 64*1024 cells
    int k16 = i >> 10;
    int n = i & 1023;
    __align__(16) __half o[16];
#pragma unroll
    for (int j = 0; j < 16; j++)
        o[posf(j)] = __float2half_rn(wo[(size_t)(k16 * 16 + j) * 1024 + n]);
    uint32_t* dst = g_woh + ((size_t)k16 * 1024 + n) * 8;
    *(uint4*)dst       = ((uint4*)o)[0];
    *(uint4*)(dst + 4) = ((uint4*)o)[1];
}

// ---------------------------------------------------------------------------
// Mask scan
// ---------------------------------------------------------------------------
__global__ __launch_bounds__(1024) void scan_mask(const int* __restrict__ mask) {
    __shared__ int buf[2][1024];
    const int b = blockIdx.x, t = threadIdx.x;
    const int m0 = mask[b * 2048 + 2 * t]     != 0;
    const int m1 = mask[b * 2048 + 2 * t + 1] != 0;
    const int sum = m0 + m1;
    buf[0][t] = sum;
    __syncthreads();
    int src = 0;
    for (int off = 1; off < 1024; off <<= 1) {
        int v = buf[src][t];
        if (t >= off) v += buf[src][t - off];
        buf[src ^ 1][t] = v;
        src ^= 1;
        __syncthreads();
    }
    const int incl = buf[src][t];
    const int nv   = buf[src][1023];
    const int excl = incl - sum;
    if (m0) g_perm[b * 2048 + excl]      = 2 * t;
    if (m1) g_perm[b * 2048 + excl + m0] = 2 * t + 1;
    if (t == 0) g_nv[b] = nv;
    const float MBv = -1.4426950408889634e9f;
    g_cmask[b * 2048 + 2 * t]     = (2 * t     < nv) ? 0.f : MBv;
    g_cmask[b * 2048 + 2 * t + 1] = (2 * t + 1 < nv) ? 0.f : MBv;
}

// ---------------------------------------------------------------------------
// Compact + convert K/V into fp16 fragment layouts.
// grid (S/16, BH), block 64.
// ---------------------------------------------------------------------------
__global__ __launch_bounds__(64) void compact_kv() {
    const int bh = blockIdx.y;
    const int b  = bh >> 4;
    const int jg = blockIdx.x;            // group of 16 keys
    const int nv   = g_nv[b];
    const int npad = (nv + 63) & ~63;
    if (jg * 16 >= npad) return;

    __shared__ int sidx[16];
    __shared__ __half sk[16][64];
    const int t = threadIdx.x;
    if (t < 16) {
        const int j = jg * 16 + t;
        sidx[t] = (j < nv) ? g_perm[b * 2048 + j] : -1;
    }
    __syncthreads();

    const __half* kh = g_kh + (size_t)bh * S_ * 64;
    const __half* vh = g_vh + (size_t)bh * S_ * 64;
    const __half hz = __float2half_rn(0.f);

#pragma unroll
    for (int j = 0; j < 16; j++)
        sk[j][t] = (sidx[j] >= 0) ? kh[(size_t)sidx[j] * 64 + t] : hz;
    __syncthreads();

    // K frag: thread = (blk, key); cell = ((bh*4+blk)*S + jg*16+key)*8 words
    {
        const int blk = t >> 4, key = t & 15;
        __align__(16) __half o[16];
#pragma unroll
        for (int j = 0; j < 16; j++) o[posf(j)] = sk[key][blk * 16 + j];
        uint32_t* dst = g_kc + ((size_t)(bh * 4 + blk) * S_ + jg * 16 + key) * 8;
        *(uint4*)dst       = ((uint4*)o)[0];
        *(uint4*)(dst + 4) = ((uint4*)o)[1];
    }

    // V frag: thread = d; cell = ((bh*(S/16)+jg)*64 + d)*8 words
    {
        __align__(16) __half o[16];
#pragma unroll
        for (int j = 0; j < 16; j++)
            o[posf(j)] = (sidx[j] >= 0) ? vh[(size_t)sidx[j] * 64 + t] : hz;
        uint32_t* dst = g_vc + (((size_t)bh * (S_ / 16) + jg) * 64 + t) * 8;
        *(uint4*)dst       = ((uint4*)o)[0];
        *(uint4*)(dst + 4) = ((uint4*)o)[1];
    }
}

// ---------------------------------------------------------------------------
// GEMM mainloop (fp16): 128x128 tile, 256 threads (8 warps, warp tile 64x32),
// k-step 32 halves, 4-stage cp.async ring.  (unchanged from r6)
// ---------------------------------------------------------------------------
#define LDA 24
#define A_BUF (128*LDA)
#define B_BUF 2048
#define STAGE_WORDS (A_BUF + B_BUF)
#define GEMM_SMEM_BYTES (4 * STAGE_WORDS * 4)

extern __shared__ uint32_t dynsmem[];

__device__ __forceinline__ void gemm_main(
    const __half* __restrict__ Ah,
    const uint32_t* __restrict__ Bw,
    int nTot,
    float acc[4][4][4])
{
    const int tid  = threadIdx.x;
    const int warp = tid >> 5;
    const int lane = tid & 31;
    const int g    = lane >> 2;
    const int tig  = lane & 3;
    const int wm   = (warp >> 2) * 64;
    const int wn   = (warp & 3) * 32;

#pragma unroll
    for (int ms = 0; ms < 4; ms++)
#pragma unroll
        for (int nt = 0; nt < 4; nt++)
#pragma unroll
            for (int r = 0; r < 4; r++) acc[ms][nt][r] = 0.f;

    const uint32_t sm = (uint32_t)__cvta_generic_to_shared(dynsmem);

    const int arow = tid >> 1;
    const int apart = tid & 1;
    const int bblk = tid >> 7;
    const int bn   = tid & 127;

    auto copy_tile = [&](int k0, int st) {
        const uint32_t base = sm + (uint32_t)st * (STAGE_WORDS * 4);
        uint32_t dA = base + (uint32_t)arow * (LDA * 4) + (uint32_t)apart * 32;
        const __half* srcA = Ah + (size_t)arow * 1024 + k0 + apart * 16;
        cpa16(dA, srcA);
        cpa16(dA + 16, srcA + 8);
        uint32_t dB = base + A_BUF * 4 + (uint32_t)(bblk * 1024 + bn * 8) * 4;
        const uint32_t* srcB = Bw + ((size_t)((k0 >> 4) + bblk) * nTot + bn) * 8;
        cpa16(dB, srcB);
        cpa16(dB + 16, srcB + 4);
        cp_commit();
    };

    copy_tile(0, 0);
    copy_tile(32, 1);
    copy_tile(64, 2);

    int st = 0;
#pragma unroll 1
    for (int k0 = 0; k0 < 1024; k0 += 32) {
        if (k0 + 64 < 1024)      cp_wait<2>();
        else if (k0 + 32 < 1024) cp_wait<1>();
        else                     cp_wait<0>();
        __syncthreads();
        if (k0 + 96 < 1024) {
            int nst = st + 3; if (nst >= 4) nst -= 4;
            copy_tile(k0 + 96, nst);
        }

        const uint32_t* A  = dynsmem + st * STAGE_WORDS;
        const uint32_t* Bt = A + A_BUF;
#pragma unroll
        for (int kk = 0; kk < 2; kk++) {
            uint32_t af[4][4];
#pragma unroll
            for (int ms = 0; ms < 4; ms++) {
                const uint32_t* ap = A + (wm + 16 * ms + g) * LDA + kk * 8 + 2 * tig;
                uint2 lo = *(const uint2*)ap;
                uint2 hi = *(const uint2*)(ap + 8 * LDA);
                af[ms][0] = lo.x; af[ms][1] = hi.x; af[ms][2] = lo.y; af[ms][3] = hi.y;
            }
#pragma unroll
            for (int nt = 0; nt < 4; nt++) {
                uint2 b = *(const uint2*)(Bt + kk * 1024 + (wn + 8 * nt + g) * 8 + 2 * tig);
#pragma unroll
                for (int ms = 0; ms < 4; ms++)
                    mma16(acc[ms][nt][0], acc[ms][nt][1], acc[ms][nt][2], acc[ms][nt][3],
                          af[ms][0], af[ms][1], af[ms][2], af[ms][3], b.x, b.y);
            }
        }
        st = (st + 1 == 4) ? 0 : st + 1;
    }
}

// ---------------------------------------------------------------------------
// Fused QKV GEMM. Q is pre-scaled by (1/8)*log2(e) for exp2-domain attention.
// ---------------------------------------------------------------------------
__global__ __launch_bounds__(256, 2) void qkv_kernel(
    const float* __restrict__ bq, const float* __restrict__ bk,
    const float* __restrict__ bv)
{
    const int m0 = blockIdx.x * 128;
    const int n0 = blockIdx.y * 128;

    float acc[4][4][4];
    gemm_main(g_xh + (size_t)m0 * 1024, g_wch + (size_t)n0 * 8, 3072, acc);

    const int tid  = threadIdx.x;
    const int warp = tid >> 5;
    const int lane = tid & 31;
    const int g    = lane >> 2;
    const int tig  = lane & 3;
    const int wm   = (warp >> 2) * 64;
    const int wn   = (warp & 3) * 32;

    const float SC = 0.18033688011112158f;   // (1/8) * log2(e)

#pragma unroll
    for (int ms = 0; ms < 4; ms++) {
#pragma unroll
        for (int nt = 0; nt < 4; nt++) {
            const int r0 = m0 + wm + 16 * ms + g;
            const int r1 = r0 + 8;
            const int C  = n0 + wn + 8 * nt + 2 * tig;
            const int which = C >> 10;
            const int h = (C >> 6) & 15;
            const int d = C & 63;
            const int b  = r0 >> 11;
            const int s0 = r0 & 2047;
            const int s1 = r1 & 2047;
            const int bh = b * 16 + h;

            const float* bp = (which == 0 ? bq : (which == 1 ? bk : bv));
            const float bx = __ldg(&bp[h * 64 + d]);
            const float by = __ldg(&bp[h * 64 + d + 1]);
            float v00 = acc[ms][nt][0] + bx, v01 = acc[ms][nt][1] + by;
            float v10 = acc[ms][nt][2] + bx, v11 = acc[ms][nt][3] + by;
            if (which == 0) { v00 *= SC; v01 *= SC; v10 *= SC; v11 *= SC; }
            __half* dst = (which == 0 ? g_qh : (which == 1 ? g_kh : g_vh))
                          + (size_t)bh * S_ * 64;
            *(__half2*)(dst + (size_t)s0 * 64 + d) = __floats2half2_rn(v00, v01);
            *(__half2*)(dst + (size_t)s1 * 64 + d) = __floats2half2_rn(v10, v11);
        }
    }
}

// ---------------------------------------------------------------------------
// Output projection
// ---------------------------------------------------------------------------
__global__ __launch_bounds__(256, 2) void proj_kernel(
    const float* __restrict__ bo, float* __restrict__ out)
{
    const int m0 = blockIdx.x * 128;
    const int n0 = blockIdx.y * 128;

    float acc[4][4][4];
    gemm_main((const __half*)g_aoh + (size_t)m0 * 1024, g_woh + (size_t)n0 * 8,
              1024, acc);

    const int tid  = threadIdx.x;
    const int warp = tid >> 5;
    const int lane = tid & 31;
    const int g    = lane >> 2;
    const int tig  = lane & 3;
    const int wm   = (warp >> 2) * 64;
    const int wn   = (warp & 3) * 32;

#pragma unroll
    for (int ms = 0; ms < 4; ms++) {
#pragma unroll
        for (int nt = 0; nt < 4; nt++) {
            const int r0 = m0 + wm + 16 * ms + g;
            const int c  = n0 + wn + 8 * nt + 2 * tig;
            const float bx = __ldg(&bo[c]);
            const float by = __ldg(&bo[c + 1]);
            *(float2*)(out + (size_t)r0 * 1024 + c) =
                make_float2(acc[ms][nt][0] + bx, acc[ms][nt][1] + by);
            *(float2*)(out + (size_t)(r0 + 8) * 1024 + c) =
                make_float2(acc[ms][nt][2] + bx, acc[ms][nt][3] + by);
        }
    }
}

// ---------------------------------------------------------------------------
// Flash attention (fp16 MMA), P kept in registers (C-frag == A-frag layout),
// h2exp2 softmax, 3-stage K/V ring with one barrier per tile.
// SMEM: 3 stages x (K 2048w + V 2048w) = 48KB
// ---------------------------------------------------------------------------
#define ASTAGE 4096
#define ATTN_SMEM_BYTES (3 * ASTAGE * 4)

__global__ __launch_bounds__(256) void attn_kernel()
{
    const int tid  = threadIdx.x;
    const int warp = tid >> 5;
    const int lane = tid & 31;
    const int g    = lane >> 2;
    const int tig  = lane & 3;

    const int bh = blockIdx.y;
    const int b  = bh >> 4;
    const int h  = bh & (H_ - 1);
    const int qbase = blockIdx.x * 128 + warp * 16;

    const int nv   = g_nv[b];
    const int npad = (nv + 63) & ~63;

    // Q A-fragments (Q already pre-scaled into exp2 domain)
    const __half* qp = g_qh + ((size_t)bh * S_ + qbase) * 64;
    uint32_t qf[4][4];
#pragma unroll
    for (int kk = 0; kk < 4; kk++) {
        qf[kk][0] = *(const uint32_t*)(qp + (size_t)g * 64 + kk * 16 + 2 * tig);
        qf[kk][1] = *(const uint32_t*)(qp + (size_t)(g + 8) * 64 + kk * 16 + 2 * tig);
        qf[kk][2] = *(const uint32_t*)(qp + (size_t)g * 64 + kk * 16 + 8 + 2 * tig);
        qf[kk][3] = *(const uint32_t*)(qp + (size_t)(g + 8) * 64 + kk * 16 + 8 + 2 * tig);
    }

    float oacc[8][4];
#pragma unroll
    for (int i = 0; i < 8; i++)
#pragma unroll
        for (int j = 0; j < 4; j++) oacc[i][j] = 0.f;
    float rm0 = -1e30f, rm1 = -1e30f;
    float rl0 = 0.f,    rl1 = 0.f;

    const uint32_t sm = (uint32_t)__cvta_generic_to_shared(dynsmem);
    const uint32_t* kc_base = g_kc + (size_t)bh * 4 * S_ * 8;
    const uint32_t* vc_base = g_vc + (size_t)bh * (S_ / 16) * 512;

    auto copy_kv = [&](int kt, int st) {
        const uint32_t base = sm + (uint32_t)st * (ASTAGE * 4);
        const int blk = tid >> 6, kx = tid & 63;
        const uint32_t* srcK = kc_base + ((size_t)blk * S_ + kt + kx) * 8;
        uint32_t dK = base + (uint32_t)(blk * 512 + kx * 8) * 4;
        cpa16(dK, srcK);
        cpa16(dK + 16, srcK + 4);
        const uint32_t* srcV = vc_base + (((size_t)(kt >> 4) + blk) * 64 + kx) * 8;
        uint32_t dV = base + 2048 * 4 + (uint32_t)(blk * 512 + kx * 8) * 4;
        cpa16(dV, srcV);
        cpa16(dV + 16, srcV + 4);
        cp_commit();
    };

    copy_kv(0, 0);
    if (64 < npad) copy_kv(64, 1);

    const float* cm = g_cmask + b * S_;
    int st = 0;
#pragma unroll 1
    for (int kt = 0; kt < npad; kt += 64) {
        if (kt + 64 < npad) cp_wait<1>();
        else                cp_wait<0>();
        __syncthreads();
        if (kt + 128 < npad) {
            int nst = st + 2; if (nst >= 3) nst -= 3;
            copy_kv(kt + 128, nst);
        }

        const uint32_t* Kb = dynsmem + st * ASTAGE;
        const uint32_t* Vb = Kb + 2048;

        // scores = Q @ K^T (already exp2-domain scaled)
        float sacc[8][4];
#pragma unroll
        for (int i = 0; i < 8; i++)
#pragma unroll
            for (int j = 0; j < 4; j++) sacc[i][j] = 0.f;
#pragma unroll
        for (int kk = 0; kk < 4; kk++) {
#pragma unroll
            for (int nt = 0; nt < 8; nt++) {
                uint2 bb = *(const uint2*)(Kb + kk * 512 + (nt * 8 + g) * 8 + 2 * tig);
                mma16(sacc[nt][0], sacc[nt][1], sacc[nt][2], sacc[nt][3],
                      qf[kk][0], qf[kk][1], qf[kk][2], qf[kk][3], bb.x, bb.y);
            }
        }

        // mask + tile row-max
        float tm0 = -1e30f, tm1 = -1e30f;
#pragma unroll
        for (int nt = 0; nt < 8; nt++) {
            const int mc = kt + nt * 8 + 2 * tig;
            const float m0v = __ldg(&cm[mc]);
            const float m1v = __ldg(&cm[mc + 1]);
            sacc[nt][0] += m0v;
            sacc[nt][1] += m1v;
            sacc[nt][2] += m0v;
            sacc[nt][3] += m1v;
            tm0 = fmaxf(tm0, fmaxf(sacc[nt][0], sacc[nt][1]));
            tm1 = fmaxf(tm1, fmaxf(sacc[nt][2], sacc[nt][3]));
        }
        tm0 = fmaxf(tm0, __shfl_xor_sync(0xffffffff, tm0, 1));
        tm0 = fmaxf(tm0, __shfl_xor_sync(0xffffffff, tm0, 2));
        tm1 = fmaxf(tm1, __shfl_xor_sync(0xffffffff, tm1, 1));
        tm1 = fmaxf(tm1, __shfl_xor_sync(0xffffffff, tm1, 2));

        const float nm0 = fmaxf(rm0, tm0);
        const float nm1 = fmaxf(rm1, tm1);
        const float c0 = exp2f(rm0 - nm0);
        const float c1 = exp2f(rm1 - nm1);
        rm0 = nm0; rm1 = nm1;
        rl0 *= c0;  rl1 *= c1;
#pragma unroll
        for (int nt = 0; nt < 8; nt++) {
            oacc[nt][0] *= c0; oacc[nt][1] *= c0;
            oacc[nt][2] *= c1; oacc[nt][3] *= c1;
        }

        // P = exp2(s - m) as packed fp16 pairs (= PV A-fragments, no SMEM)
        uint32_t pf[8][2];   // [nt][row-group]: .x-pair = cols 2tig,2tig+1
#pragma unroll
        for (int nt = 0; nt < 8; nt++) {
            __half2 p01 = h2exp2(__floats2half2_rn(sacc[nt][0] - nm0,
                                                   sacc[nt][1] - nm0));
            __half2 p23 = h2exp2(__floats2half2_rn(sacc[nt][2] - nm1,
                                                   sacc[nt][3] - nm1));
            float2 f01 = __half22float2(p01);
            float2 f23 = __half22float2(p23);
            rl0 += f01.x + f01.y;
            rl1 += f23.x + f23.y;
            pf[nt][0] = h2u(p01);
            pf[nt][1] = h2u(p23);
        }

        // O += P @ V : A-frags come straight from pf
#pragma unroll
        for (int kk = 0; kk < 4; kk++) {
            const uint32_t a0 = pf[2 * kk][0];
            const uint32_t a1 = pf[2 * kk][1];
            const uint32_t a2 = pf[2 * kk + 1][0];
            const uint32_t a3 = pf[2 * kk + 1][1];
#pragma unroll
            for (int nt = 0; nt < 8; nt++) {
                uint2 bb = *(const uint2*)(Vb + kk * 512 + (nt * 8 + g) * 8 + 2 * tig);
                mma16(oacc[nt][0], oacc[nt][1], oacc[nt][2], oacc[nt][3],
                      a0, a1, a2, a3, bb.x, bb.y);
            }
        }
        st = (st + 1 == 3) ? 0 : st + 1;
    }

    rl0 += __shfl_xor_sync(0xffffffff, rl0, 1);
    rl0 += __shfl_xor_sync(0xffffffff, rl0, 2);
    rl1 += __shfl_xor_sync(0xffffffff, rl1, 1);
    rl1 += __shfl_xor_sync(0xffffffff, rl1, 2);
    const float inv0 = 1.f / rl0;
    const float inv1 = 1.f / rl1;

    // write attention output in permuted fp16 layout for proj (row = 512 words)
    const size_t row0 = (size_t)b * S_ + qbase + g;
#pragma unroll
    for (int nt = 0; nt < 8; nt++) {
        const int C = h * 64 + nt * 8 + 2 * tig;
        const int j = C & 15;
        const int w = (C >> 4) * 8 + (j & 6) + (j >> 3);
        g_aoh[row0 * 512 + w] =
            h2u(__floats2half2_rn(oacc[nt][0] * inv0, oacc[nt][1] * inv0));
        g_aoh[(row0 + 8) * 512 + w] =
            h2u(__floats2half2_rn(oacc[nt][2] * inv1, oacc[nt][3] * inv1));
    }
}

// ---------------------------------------------------------------------------
extern "C" void kernel_launch(void* const* d_in, const int* in_sizes, int n_in,
                              void* d_out, int out_size)
{
    const float* x    = (const float*)d_in[0];
    const int*   mask = (const int*)  d_in[1];
    const float* wq   = (const float*)d_in[2];
    const float* bq   = (const float*)d_in[3];
    const float* wk   = (const float*)d_in[4];
    const float* bk   = (const float*)d_in[5];
    const float* wv   = (const float*)d_in[6];
    const float* bv   = (const float*)d_in[7];
    const float* wo   = (const float*)d_in[8];
    const float* bo   = (const float*)d_in[9];
    float* out = (float*)d_out;

    static bool attrs_set = false;
    if (!attrs_set) {
        cudaFuncSetAttribute(qkv_kernel,  cudaFuncAttributeMaxDynamicSharedMemorySize, GEMM_SMEM_BYTES);
        cudaFuncSetAttribute(proj_kernel, cudaFuncAttributeMaxDynamicSharedMemorySize, GEMM_SMEM_BYTES);
        cudaFuncSetAttribute(attn_kernel, cudaFuncAttributeMaxDynamicSharedMemorySize, ATTN_SMEM_BYTES);
        attrs_set = true;
    }

    prep_x <<<(B_ * S_ * 64) / 256, 256>>>(x);
    prep_wc<<<(64 * 3072) / 256, 256>>>(wq, wk, wv);
    prep_wo<<<(64 * 1024) / 256, 256>>>(wo);
    scan_mask<<<B_, 1024>>>(mask);

    dim3 g1(S_ * B_ / 128, 3072 / 128);
    qkv_kernel<<<g1, 256, GEMM_SMEM_BYTES>>>(bq, bk, bv);

    dim3 gc(S_ / 16, BH_);
    compact_kv<<<gc, 64>>>();

    dim3 g2(S_ / 128, BH_);
    attn_kernel<<<g2, 256, ATTN_SMEM_BYTES>>>();

    dim3 g3((B_ * S_) / 128, E_ / 128);
    proj_kernel<<<g3, 256, GEMM_SMEM_BYTES>>>(bo, out);
}